// round 1
// baseline (speedup 1.0000x reference)
#include <cuda_runtime.h>
#include <math.h>

#define D_MODEL 1024
#define NH      16
#define DH      64
#define BATCH   2
#define T       2048
#define BT      4096        // BATCH*T
#define QKV_N   3072

// Scratch (static device allocations are allowed; cudaMalloc is not)
__device__ float g_h[BT * D_MODEL];        // layernorm output
__device__ float g_qkv[(size_t)BT * QKV_N]; // fused qkv
__device__ float g_ao[BT * D_MODEL];       // attention output [token, D]

// ---------------------------------------------------------------------------
// LayerNorm: one block per token, 256 threads, D=1024 (4 elems/thread)
// ---------------------------------------------------------------------------
__global__ void ln_kernel(const float* __restrict__ x, const float* __restrict__ gam,
                          const float* __restrict__ bet, float* __restrict__ out) {
    int row = blockIdx.x;
    const float* xr = x + (size_t)row * D_MODEL;
    float* orow = out + (size_t)row * D_MODEL;
    float v[4];
    float s = 0.f, s2 = 0.f;
#pragma unroll
    for (int i = 0; i < 4; i++) {
        v[i] = xr[threadIdx.x + i * 256];
        s += v[i];
        s2 += v[i] * v[i];
    }
#pragma unroll
    for (int o = 16; o > 0; o >>= 1) {
        s  += __shfl_xor_sync(~0u, s, o);
        s2 += __shfl_xor_sync(~0u, s2, o);
    }
    __shared__ float rs[8], rs2[8];
    int wid = threadIdx.x >> 5, lid = threadIdx.x & 31;
    if (lid == 0) { rs[wid] = s; rs2[wid] = s2; }
    __syncthreads();
    s = 0.f; s2 = 0.f;
#pragma unroll
    for (int i = 0; i < 8; i++) { s += rs[i]; s2 += rs2[i]; }
    float mu  = s * (1.f / D_MODEL);
    float var = s2 * (1.f / D_MODEL) - mu * mu;
    float inv = rsqrtf(var + 1e-5f);
#pragma unroll
    for (int i = 0; i < 4; i++) {
        int c = threadIdx.x + i * 256;
        orow[c] = (v[i] - mu) * inv * gam[c] + bet[c];
    }
}

// ---------------------------------------------------------------------------
// Generic fp32 GEMM: C[M,N] = A[M,K] @ W[K,N] + bias (+ residual)
// BM=BN=128, BK=16, 256 threads, 8x8 register tile. Dims must divide tiles.
// ---------------------------------------------------------------------------
template <bool RES>
__global__ void gemm_kernel(const float* __restrict__ A, const float* __restrict__ W,
                            const float* __restrict__ bias, const float* __restrict__ res,
                            float* __restrict__ C, int M, int N, int K) {
    __shared__ float As[16][128];
    __shared__ float Bs[16][128];
    int bm = blockIdx.y, bn = blockIdx.x;
    int tid = threadIdx.x;
    int tr = tid >> 4, tc = tid & 15;
    float acc[8][8];
#pragma unroll
    for (int i = 0; i < 8; i++)
#pragma unroll
        for (int j = 0; j < 8; j++) acc[i][j] = 0.f;

    const float* Ab = A + (size_t)bm * 128 * K;

    for (int k0 = 0; k0 < K; k0 += 16) {
#pragma unroll
        for (int it = 0; it < 2; it++) {
            int idx = tid + it * 256;      // 0..511
            int row = idx >> 2;
            int c4  = idx & 3;
            float4 va = *(const float4*)&Ab[(size_t)row * K + k0 + c4 * 4];
            As[c4 * 4 + 0][row] = va.x;
            As[c4 * 4 + 1][row] = va.y;
            As[c4 * 4 + 2][row] = va.z;
            As[c4 * 4 + 3][row] = va.w;
        }
#pragma unroll
        for (int it = 0; it < 2; it++) {
            int idx = tid + it * 256;
            int row = idx >> 5;
            int c4  = idx & 31;
            *(float4*)&Bs[row][c4 * 4] =
                *(const float4*)&W[(size_t)(k0 + row) * N + bn * 128 + c4 * 4];
        }
        __syncthreads();
#pragma unroll
        for (int k = 0; k < 16; k++) {
            float ra[8], rb[8];
            *(float4*)&ra[0] = *(const float4*)&As[k][tr * 8];
            *(float4*)&ra[4] = *(const float4*)&As[k][tr * 8 + 4];
            *(float4*)&rb[0] = *(const float4*)&Bs[k][tc * 8];
            *(float4*)&rb[4] = *(const float4*)&Bs[k][tc * 8 + 4];
#pragma unroll
            for (int i = 0; i < 8; i++)
#pragma unroll
                for (int j = 0; j < 8; j++) acc[i][j] += ra[i] * rb[j];
        }
        __syncthreads();
    }

#pragma unroll
    for (int i = 0; i < 8; i++) {
        int r = bm * 128 + tr * 8 + i;
#pragma unroll
        for (int j4 = 0; j4 < 2; j4++) {
            int c = bn * 128 + tc * 8 + j4 * 4;
            float4 o;
            o.x = acc[i][j4 * 4 + 0] + bias[c + 0];
            o.y = acc[i][j4 * 4 + 1] + bias[c + 1];
            o.z = acc[i][j4 * 4 + 2] + bias[c + 2];
            o.w = acc[i][j4 * 4 + 3] + bias[c + 3];
            if (RES) {
                float4 rr = *(const float4*)&res[(size_t)r * N + c];
                o.x += rr.x; o.y += rr.y; o.z += rr.z; o.w += rr.w;
            }
            *(float4*)&C[(size_t)r * N + c] = o;
        }
    }
}

// ---------------------------------------------------------------------------
// Scores: S[bh, q, k] = (Q . K)/8 with causal mask (masked entries -> 0).
// 64x64 tile per block; fully-masked tiles just write zeros.
// ---------------------------------------------------------------------------
__global__ void scores_kernel(const float* __restrict__ qkv, float* __restrict__ attn) {
    int kt = blockIdx.x, qt = blockIdx.y, bh = blockIdx.z;
    int b = bh >> 4, h = bh & 15;
    int tid = threadIdx.x;
    float* ablk = attn + ((size_t)bh * T + qt * 64) * T + kt * 64;

    if (kt > qt) {
        int r = tid >> 4, c4 = tid & 15;
        float4 z = make_float4(0.f, 0.f, 0.f, 0.f);
#pragma unroll
        for (int i = 0; i < 4; i++)
            *(float4*)&ablk[(size_t)(r + i * 16) * T + c4 * 4] = z;
        return;
    }

    __shared__ float Qs[64][68];
    __shared__ float Ks[64][68];
    const float* qb = qkv + ((size_t)(b * T + qt * 64)) * QKV_N + h * 64;
    const float* kb = qkv + ((size_t)(b * T + kt * 64)) * QKV_N + D_MODEL + h * 64;

    int lr = tid >> 4, lc = tid & 15;
#pragma unroll
    for (int i = 0; i < 4; i++) {
        int r = lr + i * 16;
        *(float4*)&Qs[r][lc * 4] = *(const float4*)&qb[(size_t)r * QKV_N + lc * 4];
        *(float4*)&Ks[r][lc * 4] = *(const float4*)&kb[(size_t)r * QKV_N + lc * 4];
    }
    __syncthreads();

    int tr = tid >> 4, tc = tid & 15;
    float acc[4][4];
#pragma unroll
    for (int i = 0; i < 4; i++)
#pragma unroll
        for (int j = 0; j < 4; j++) acc[i][j] = 0.f;

#pragma unroll
    for (int d = 0; d < 64; d++) {
        float qa[4], ka[4];
#pragma unroll
        for (int i = 0; i < 4; i++) qa[i] = Qs[tr * 4 + i][d];
#pragma unroll
        for (int j = 0; j < 4; j++) ka[j] = Ks[tc * 4 + j][d];
#pragma unroll
        for (int i = 0; i < 4; i++)
#pragma unroll
            for (int j = 0; j < 4; j++) acc[i][j] += qa[i] * ka[j];
    }

#pragma unroll
    for (int i = 0; i < 4; i++) {
        int q = qt * 64 + tr * 4 + i;
        float4 o;
        int kcol = kt * 64 + tc * 4;
        o.x = (kcol + 0 <= q) ? acc[i][0] * 0.125f : 0.f;
        o.y = (kcol + 1 <= q) ? acc[i][1] * 0.125f : 0.f;
        o.z = (kcol + 2 <= q) ? acc[i][2] * 0.125f : 0.f;
        o.w = (kcol + 3 <= q) ? acc[i][3] * 0.125f : 0.f;
        *(float4*)&ablk[(size_t)(tr * 4 + i) * T + tc * 4] = o;
    }
}

// ---------------------------------------------------------------------------
// Softmax over valid prefix [0, q] of each row. Cols > q already 0.
// ---------------------------------------------------------------------------
__global__ void softmax_kernel(float* __restrict__ attn) {
    int row = blockIdx.x;               // bh*T + q
    int q = row & (T - 1);
    int n = q + 1;
    float* p = attn + (size_t)row * T;
    int tid = threadIdx.x;

    __shared__ float smax[8], ssum[8];
    int wid = tid >> 5, lid = tid & 31;

    float m = -1e30f;
    for (int i = tid; i < n; i += 256) m = fmaxf(m, p[i]);
#pragma unroll
    for (int o = 16; o > 0; o >>= 1) m = fmaxf(m, __shfl_xor_sync(~0u, m, o));
    if (lid == 0) smax[wid] = m;
    __syncthreads();
    m = smax[0];
#pragma unroll
    for (int i = 1; i < 8; i++) m = fmaxf(m, smax[i]);

    float s = 0.f;
    for (int i = tid; i < n; i += 256) s += __expf(p[i] - m);
#pragma unroll
    for (int o = 16; o > 0; o >>= 1) s += __shfl_xor_sync(~0u, s, o);
    if (lid == 0) ssum[wid] = s;
    __syncthreads();
    s = 0.f;
#pragma unroll
    for (int i = 0; i < 8; i++) s += ssum[i];
    float inv = 1.f / s;

    for (int i = tid; i < n; i += 256) p[i] = __expf(p[i] - m) * inv;
}

// ---------------------------------------------------------------------------
// O = P @ V per (bh), 64x64 output tile per block, causal k-loop.
// ---------------------------------------------------------------------------
__global__ void av_kernel(const float* __restrict__ attn, const float* __restrict__ qkv,
                          float* __restrict__ out) {
    int qt = blockIdx.x, bh = blockIdx.y;
    int b = bh >> 4, h = bh & 15;
    int tid = threadIdx.x;
    __shared__ float Ps[64][68];
    __shared__ float Vs[64][68];

    const float* arow = attn + ((size_t)bh * T + qt * 64) * T;
    const float* vb = qkv + ((size_t)b * T) * QKV_N + 2 * D_MODEL + h * 64;

    int lr = tid >> 4, lc = tid & 15;
    int tr = tid >> 4, tc = tid & 15;
    float acc[4][4];
#pragma unroll
    for (int i = 0; i < 4; i++)
#pragma unroll
        for (int j = 0; j < 4; j++) acc[i][j] = 0.f;

    for (int kt = 0; kt <= qt; kt++) {
#pragma unroll
        for (int i = 0; i < 4; i++) {
            int r = lr + i * 16;
            *(float4*)&Ps[r][lc * 4] = *(const float4*)&arow[(size_t)r * T + kt * 64 + lc * 4];
            *(float4*)&Vs[r][lc * 4] = *(const float4*)&vb[(size_t)(kt * 64 + r) * QKV_N + lc * 4];
        }
        __syncthreads();
#pragma unroll
        for (int k = 0; k < 64; k++) {
            float pa[4], va[4];
#pragma unroll
            for (int i = 0; i < 4; i++) pa[i] = Ps[tr * 4 + i][k];
            *(float4*)&va[0] = *(const float4*)&Vs[k][tc * 4];
#pragma unroll
            for (int i = 0; i < 4; i++)
#pragma unroll
                for (int j = 0; j < 4; j++) acc[i][j] += pa[i] * va[j];
        }
        __syncthreads();
    }

#pragma unroll
    for (int i = 0; i < 4; i++) {
        int tok = b * T + qt * 64 + tr * 4 + i;
        *(float4*)&out[(size_t)tok * D_MODEL + h * 64 + tc * 4] =
            make_float4(acc[i][0], acc[i][1], acc[i][2], acc[i][3]);
    }
}

// ---------------------------------------------------------------------------
extern "C" void kernel_launch(void* const* d_in, const int* in_sizes, int n_in,
                              void* d_out, int out_size) {
    (void)in_sizes; (void)n_in; (void)out_size;
    const float* x     = (const float*)d_in[0];
    const float* ln_g  = (const float*)d_in[1];
    const float* ln_b  = (const float*)d_in[2];
    const float* qkv_w = (const float*)d_in[3];
    const float* qkv_b = (const float*)d_in[4];
    const float* out_w = (const float*)d_in[5];
    const float* out_b = (const float*)d_in[6];

    float* xout = (float*)d_out;
    float* attn = xout + (size_t)BT * D_MODEL;

    static float *p_h = nullptr, *p_qkv = nullptr, *p_ao = nullptr;
    if (!p_h) {
        cudaGetSymbolAddress((void**)&p_h, g_h);
        cudaGetSymbolAddress((void**)&p_qkv, g_qkv);
        cudaGetSymbolAddress((void**)&p_ao, g_ao);
    }

    ln_kernel<<<BT, 256>>>(x, ln_g, ln_b, p_h);
    gemm_kernel<false><<<dim3(QKV_N / 128, BT / 128), 256>>>(
        p_h, qkv_w, qkv_b, nullptr, p_qkv, BT, QKV_N, D_MODEL);
    scores_kernel<<<dim3(32, 32, 32), 256>>>(p_qkv, attn);
    softmax_kernel<<<BATCH * NH * T, 256>>>(attn);
    av_kernel<<<dim3(32, 32), 256>>>(attn, p_qkv, p_ao);
    gemm_kernel<true><<<dim3(D_MODEL / 128, BT / 128), 256>>>(
        p_ao, out_w, out_b, x, xout, BT, D_MODEL, D_MODEL);
}

// round 3
// speedup vs baseline: 1.2856x; 1.2856x over previous
#include <cuda_runtime.h>
#include <cuda_bf16.h>
#include <cstdint>
#include <math.h>

#define D_MODEL 1024
#define NH      16
#define DH      64
#define BATCH   2
#define T       2048
#define BT      4096
#define QKV_N   3072

// ---------------------------------------------------------------------------
// Scratch (static device arrays; no cudaMalloc allowed)
// ---------------------------------------------------------------------------
__device__ __nv_bfloat16 g_h_hi[(size_t)BT * D_MODEL];
__device__ __nv_bfloat16 g_h_lo[(size_t)BT * D_MODEL];
__device__ float         g_qkv[(size_t)BT * QKV_N];
__device__ __nv_bfloat16 g_wq_hi[(size_t)QKV_N * D_MODEL];   // qkv_w^T [N][K]
__device__ __nv_bfloat16 g_wq_lo[(size_t)QKV_N * D_MODEL];
__device__ __nv_bfloat16 g_wo_hi[(size_t)D_MODEL * D_MODEL]; // out_w^T [N][K]
__device__ __nv_bfloat16 g_wo_lo[(size_t)D_MODEL * D_MODEL];
__device__ __nv_bfloat16 g_ao_hi[(size_t)BT * D_MODEL];
__device__ __nv_bfloat16 g_ao_lo[(size_t)BT * D_MODEL];

// ---------------------------------------------------------------------------
// Warp MMA helpers (baseline PTX, legal on sm_103 non-'a' target)
// ---------------------------------------------------------------------------
__device__ __forceinline__ uint32_t smem_u32(const void* p) {
    uint32_t a;
    asm("{ .reg .u64 t; cvta.to.shared.u64 t, %1; cvt.u32.u64 %0, t; }" : "=r"(a) : "l"(p));
    return a;
}
#define LDSM4(r0, r1, r2, r3, addr)                                              \
    asm volatile("ldmatrix.sync.aligned.m8n8.x4.shared.b16 {%0,%1,%2,%3}, [%4];" \
                 : "=r"(r0), "=r"(r1), "=r"(r2), "=r"(r3) : "r"(addr))
#define MMA16816(c, a, b0, b1)                                                   \
    asm volatile("mma.sync.aligned.m16n8k16.row.col.f32.bf16.bf16.f32 "          \
                 "{%0,%1,%2,%3}, {%4,%5,%6,%7}, {%8,%9}, {%0,%1,%2,%3};"         \
                 : "+f"((c)[0]), "+f"((c)[1]), "+f"((c)[2]), "+f"((c)[3])        \
                 : "r"((a)[0]), "r"((a)[1]), "r"((a)[2]), "r"((a)[3]),           \
                   "r"(b0), "r"(b1))

// ---------------------------------------------------------------------------
// LayerNorm -> bf16 hi/lo split
// ---------------------------------------------------------------------------
__global__ void ln_kernel(const float* __restrict__ x, const float* __restrict__ gam,
                          const float* __restrict__ bet,
                          __nv_bfloat16* __restrict__ ohi, __nv_bfloat16* __restrict__ olo) {
    int row = blockIdx.x;
    const float* xr = x + (size_t)row * D_MODEL;
    float v[4];
    float s = 0.f, s2 = 0.f;
#pragma unroll
    for (int i = 0; i < 4; i++) {
        v[i] = xr[threadIdx.x + i * 256];
        s += v[i]; s2 += v[i] * v[i];
    }
#pragma unroll
    for (int o = 16; o > 0; o >>= 1) {
        s  += __shfl_xor_sync(~0u, s, o);
        s2 += __shfl_xor_sync(~0u, s2, o);
    }
    __shared__ float rs[8], rs2[8];
    int wid = threadIdx.x >> 5, lid = threadIdx.x & 31;
    if (lid == 0) { rs[wid] = s; rs2[wid] = s2; }
    __syncthreads();
    s = 0.f; s2 = 0.f;
#pragma unroll
    for (int i = 0; i < 8; i++) { s += rs[i]; s2 += rs2[i]; }
    float mu  = s * (1.f / D_MODEL);
    float var = s2 * (1.f / D_MODEL) - mu * mu;
    float inv = rsqrtf(var + 1e-5f);
#pragma unroll
    for (int i = 0; i < 4; i++) {
        int c = threadIdx.x + i * 256;
        float y = (v[i] - mu) * inv * gam[c] + bet[c];
        __nv_bfloat16 h = __float2bfloat16(y);
        ohi[(size_t)row * D_MODEL + c] = h;
        olo[(size_t)row * D_MODEL + c] = __float2bfloat16(y - __bfloat162float(h));
    }
}

// ---------------------------------------------------------------------------
// Transpose + bf16 split: W[K][N] -> out[N][K] (hi, lo)
// ---------------------------------------------------------------------------
__global__ void tsplit_kernel(const float* __restrict__ W,
                              __nv_bfloat16* __restrict__ hi, __nv_bfloat16* __restrict__ lo,
                              int K, int N) {
    __shared__ float t[32][33];
    int n0 = blockIdx.x * 32, k0 = blockIdx.y * 32;
    int tx = threadIdx.x, ty = threadIdx.y;   // (32, 8)
#pragma unroll
    for (int j = 0; j < 4; j++)
        t[ty + j * 8][tx] = W[(size_t)(k0 + ty + j * 8) * N + n0 + tx];
    __syncthreads();
#pragma unroll
    for (int j = 0; j < 4; j++) {
        float v = t[tx][ty + j * 8];                    // = W[k0+tx][n0+ty+j*8]
        size_t o = (size_t)(n0 + ty + j * 8) * K + k0 + tx;
        __nv_bfloat16 h = __float2bfloat16(v);
        hi[o] = h;
        lo[o] = __float2bfloat16(v - __bfloat162float(h));
    }
}

// ---------------------------------------------------------------------------
// HMMA bf16-split GEMM: C[M,N] = (Ah+Al)[M,K] @ (Bh+Bl)[N,K]^T + bias (+res)
// 128x128x32 block tile, 256 thr (8 warps, 4x2), warp tile 32x64.
// ---------------------------------------------------------------------------
#define SA 40   // smem stride in bf16 (80B rows: 16B-aligned, ldmatrix conflict-free)

template <bool RES>
__global__ void __launch_bounds__(256) gemm_mma(
    const __nv_bfloat16* __restrict__ Ah, const __nv_bfloat16* __restrict__ Al,
    const __nv_bfloat16* __restrict__ Bh, const __nv_bfloat16* __restrict__ Bl,
    const float* __restrict__ bias, const float* __restrict__ res,
    float* __restrict__ C, int N, int K) {
    __shared__ __align__(16) __nv_bfloat16 sAh[128 * SA];
    __shared__ __align__(16) __nv_bfloat16 sAl[128 * SA];
    __shared__ __align__(16) __nv_bfloat16 sBh[128 * SA];
    __shared__ __align__(16) __nv_bfloat16 sBl[128 * SA];

    int tid = threadIdx.x;
    int wid = tid >> 5, lane = tid & 31;
    int wm = wid & 3, wn = wid >> 2;         // warp grid 4 (M) x 2 (N)
    int bm = blockIdx.y, bn = blockIdx.x;

    uint32_t uAh = smem_u32(sAh), uAl = smem_u32(sAl);
    uint32_t uBh = smem_u32(sBh), uBl = smem_u32(sBl);

    // ldmatrix lane address components
    int a_row = wm * 32 + ((lane >> 3) & 1) * 8 + (lane & 7); // + ma*16
    int a_kc  = (lane >> 4) * 8;                               // + ks*16
    int b_row = wn * 64 + (lane >> 4) * 8 + (lane & 7);        // + nb2*16
    int b_kc  = ((lane >> 3) & 1) * 8;                         // + ks*16

    float c[2][8][4];
#pragma unroll
    for (int i = 0; i < 2; i++)
#pragma unroll
        for (int j = 0; j < 8; j++)
#pragma unroll
            for (int q = 0; q < 4; q++) c[i][j][q] = 0.f;

    int ldr = tid >> 2, ldc = (tid & 3) * 8;  // global/smem copy: 64 rows per 256-thr pass

    for (int c0 = 0; c0 < K; c0 += 32) {
        __syncthreads();
#pragma unroll
        for (int it = 0; it < 2; it++) {
            int r = ldr + it * 64;
            size_t ga = (size_t)(bm * 128 + r) * K + c0 + ldc;
            size_t gb = (size_t)(bn * 128 + r) * K + c0 + ldc;
            int so = r * SA + ldc;
            *(uint4*)&sAh[so] = *(const uint4*)&Ah[ga];
            *(uint4*)&sAl[so] = *(const uint4*)&Al[ga];
            *(uint4*)&sBh[so] = *(const uint4*)&Bh[gb];
            *(uint4*)&sBl[so] = *(const uint4*)&Bl[gb];
        }
        __syncthreads();

#pragma unroll
        for (int ks = 0; ks < 2; ks++) {
            uint32_t ah[2][4], al[2][4], bh[4][4], bl[4][4];
#pragma unroll
            for (int ma = 0; ma < 2; ma++) {
                uint32_t off = ((a_row + ma * 16) * SA + a_kc + ks * 16) * 2;
                LDSM4(ah[ma][0], ah[ma][1], ah[ma][2], ah[ma][3], uAh + off);
                LDSM4(al[ma][0], al[ma][1], al[ma][2], al[ma][3], uAl + off);
            }
#pragma unroll
            for (int nb2 = 0; nb2 < 4; nb2++) {
                uint32_t off = ((b_row + nb2 * 16) * SA + b_kc + ks * 16) * 2;
                LDSM4(bh[nb2][0], bh[nb2][1], bh[nb2][2], bh[nb2][3], uBh + off);
                LDSM4(bl[nb2][0], bl[nb2][1], bl[nb2][2], bl[nb2][3], uBl + off);
            }
#pragma unroll
            for (int ma = 0; ma < 2; ma++)
#pragma unroll
                for (int nb = 0; nb < 8; nb++) {
                    int n2 = nb >> 1, o = (nb & 1) * 2;
                    MMA16816(c[ma][nb], ah[ma], bh[n2][o], bh[n2][o + 1]);
                    MMA16816(c[ma][nb], ah[ma], bl[n2][o], bl[n2][o + 1]);
                    MMA16816(c[ma][nb], al[ma], bh[n2][o], bh[n2][o + 1]);
                }
        }
    }

    // Epilogue
    int r0 = bm * 128 + wm * 32 + (lane >> 2);
#pragma unroll
    for (int ma = 0; ma < 2; ma++) {
#pragma unroll
        for (int nb = 0; nb < 8; nb++) {
            int col = bn * 128 + wn * 64 + nb * 8 + (lane & 3) * 2;
            int ra = r0 + ma * 16, rb = ra + 8;
            float2 o0, o1;
            o0.x = c[ma][nb][0] + bias[col];
            o0.y = c[ma][nb][1] + bias[col + 1];
            o1.x = c[ma][nb][2] + bias[col];
            o1.y = c[ma][nb][3] + bias[col + 1];
            if (RES) {
                float2 r2a = *(const float2*)&res[(size_t)ra * N + col];
                float2 r2b = *(const float2*)&res[(size_t)rb * N + col];
                o0.x += r2a.x; o0.y += r2a.y;
                o1.x += r2b.x; o1.y += r2b.y;
            }
            *(float2*)&C[(size_t)ra * N + col] = o0;
            *(float2*)&C[(size_t)rb * N + col] = o1;
        }
    }
}

// ---------------------------------------------------------------------------
// Scores (verified round-1 code)
// ---------------------------------------------------------------------------
__global__ void scores_kernel(const float* __restrict__ qkv, float* __restrict__ attn) {
    int kt = blockIdx.x, qt = blockIdx.y, bh = blockIdx.z;
    int b = bh >> 4, h = bh & 15;
    int tid = threadIdx.x;
    float* ablk = attn + ((size_t)bh * T + qt * 64) * T + kt * 64;

    if (kt > qt) {
        int r = tid >> 4, c4 = tid & 15;
        float4 z = make_float4(0.f, 0.f, 0.f, 0.f);
#pragma unroll
        for (int i = 0; i < 4; i++)
            *(float4*)&ablk[(size_t)(r + i * 16) * T + c4 * 4] = z;
        return;
    }

    __shared__ float Qs[64][68];
    __shared__ float Ks[64][68];
    const float* qb = qkv + ((size_t)(b * T + qt * 64)) * QKV_N + h * 64;
    const float* kb = qkv + ((size_t)(b * T + kt * 64)) * QKV_N + D_MODEL + h * 64;

    int lr = tid >> 4, lc = tid & 15;
#pragma unroll
    for (int i = 0; i < 4; i++) {
        int r = lr + i * 16;
        *(float4*)&Qs[r][lc * 4] = *(const float4*)&qb[(size_t)r * QKV_N + lc * 4];
        *(float4*)&Ks[r][lc * 4] = *(const float4*)&kb[(size_t)r * QKV_N + lc * 4];
    }
    __syncthreads();

    int tr = tid >> 4, tc = tid & 15;
    float acc[4][4];
#pragma unroll
    for (int i = 0; i < 4; i++)
#pragma unroll
        for (int j = 0; j < 4; j++) acc[i][j] = 0.f;

#pragma unroll
    for (int d = 0; d < 64; d++) {
        float qa[4], ka[4];
#pragma unroll
        for (int i = 0; i < 4; i++) qa[i] = Qs[tr * 4 + i][d];
#pragma unroll
        for (int j = 0; j < 4; j++) ka[j] = Ks[tc * 4 + j][d];
#pragma unroll
        for (int i = 0; i < 4; i++)
#pragma unroll
            for (int j = 0; j < 4; j++) acc[i][j] += qa[i] * ka[j];
    }

#pragma unroll
    for (int i = 0; i < 4; i++) {
        int q = qt * 64 + tr * 4 + i;
        float4 o;
        int kcol = kt * 64 + tc * 4;
        o.x = (kcol + 0 <= q) ? acc[i][0] * 0.125f : 0.f;
        o.y = (kcol + 1 <= q) ? acc[i][1] * 0.125f : 0.f;
        o.z = (kcol + 2 <= q) ? acc[i][2] * 0.125f : 0.f;
        o.w = (kcol + 3 <= q) ? acc[i][3] * 0.125f : 0.f;
        *(float4*)&ablk[(size_t)(tr * 4 + i) * T + tc * 4] = o;
    }
}

// ---------------------------------------------------------------------------
// Softmax: register-resident, single global read + single write
// ---------------------------------------------------------------------------
__global__ void softmax_kernel(float* __restrict__ attn) {
    int row = blockIdx.x;               // bh*T + q
    int q = row & (T - 1);
    int n = q + 1;
    float* p = attn + (size_t)row * T;
    int tid = threadIdx.x;

    float v[8];
    float m = -1e30f;
#pragma unroll
    for (int j = 0; j < 8; j++) {
        int i = tid + j * 256;
        v[j] = (i < n) ? p[i] : -1e30f;
        m = fmaxf(m, v[j]);
    }
    __shared__ float smax[8], ssum[8];
    int wid = tid >> 5, lid = tid & 31;
#pragma unroll
    for (int o = 16; o > 0; o >>= 1) m = fmaxf(m, __shfl_xor_sync(~0u, m, o));
    if (lid == 0) smax[wid] = m;
    __syncthreads();
    m = smax[0];
#pragma unroll
    for (int i = 1; i < 8; i++) m = fmaxf(m, smax[i]);

    float s = 0.f;
#pragma unroll
    for (int j = 0; j < 8; j++) {
        v[j] = __expf(v[j] - m);        // invalid slots underflow to ~0
        s += v[j];
    }
#pragma unroll
    for (int o = 16; o > 0; o >>= 1) s += __shfl_xor_sync(~0u, s, o);
    if (lid == 0) ssum[wid] = s;
    __syncthreads();
    s = 0.f;
#pragma unroll
    for (int i = 0; i < 8; i++) s += ssum[i];
    float inv = 1.f / s;

#pragma unroll
    for (int j = 0; j < 8; j++) {
        int i = tid + j * 256;
        if (i < n) p[i] = v[j] * inv;
    }
}

// ---------------------------------------------------------------------------
// O = P @ V, epilogue emits bf16 hi/lo for the HMMA out-projection
// ---------------------------------------------------------------------------
__global__ void av_kernel(const float* __restrict__ attn, const float* __restrict__ qkv,
                          __nv_bfloat16* __restrict__ ohi, __nv_bfloat16* __restrict__ olo) {
    int qt = blockIdx.x, bh = blockIdx.y;
    int b = bh >> 4, h = bh & 15;
    int tid = threadIdx.x;
    __shared__ float Ps[64][68];
    __shared__ float Vs[64][68];

    const float* arow = attn + ((size_t)bh * T + qt * 64) * T;
    const float* vb = qkv + ((size_t)b * T) * QKV_N + 2 * D_MODEL + h * 64;

    int lr = tid >> 4, lc = tid & 15;
    int tr = tid >> 4, tc = tid & 15;
    float acc[4][4];
#pragma unroll
    for (int i = 0; i < 4; i++)
#pragma unroll
        for (int j = 0; j < 4; j++) acc[i][j] = 0.f;

    for (int kt = 0; kt <= qt; kt++) {
#pragma unroll
        for (int i = 0; i < 4; i++) {
            int r = lr + i * 16;
            *(float4*)&Ps[r][lc * 4] = *(const float4*)&arow[(size_t)r * T + kt * 64 + lc * 4];
            *(float4*)&Vs[r][lc * 4] = *(const float4*)&vb[(size_t)(kt * 64 + r) * QKV_N + lc * 4];
        }
        __syncthreads();
#pragma unroll
        for (int k = 0; k < 64; k++) {
            float pa[4], va[4];
#pragma unroll
            for (int i = 0; i < 4; i++) pa[i] = Ps[tr * 4 + i][k];
            *(float4*)&va[0] = *(const float4*)&Vs[k][tc * 4];
#pragma unroll
            for (int i = 0; i < 4; i++)
#pragma unroll
                for (int j = 0; j < 4; j++) acc[i][j] += pa[i] * va[j];
        }
        __syncthreads();
    }

#pragma unroll
    for (int i = 0; i < 4; i++) {
        int tok = b * T + qt * 64 + tr * 4 + i;
        size_t base = (size_t)tok * D_MODEL + h * 64 + tc * 4;
#pragma unroll
        for (int j = 0; j < 4; j++) {
            float y = acc[i][j];
            __nv_bfloat16 hi = __float2bfloat16(y);
            ohi[base + j] = hi;
            olo[base + j] = __float2bfloat16(y - __bfloat162float(hi));
        }
    }
}

// ---------------------------------------------------------------------------
extern "C" void kernel_launch(void* const* d_in, const int* in_sizes, int n_in,
                              void* d_out, int out_size) {
    (void)in_sizes; (void)n_in; (void)out_size;
    const float* x     = (const float*)d_in[0];
    const float* ln_g  = (const float*)d_in[1];
    const float* ln_b  = (const float*)d_in[2];
    const float* qkv_w = (const float*)d_in[3];
    const float* qkv_b = (const float*)d_in[4];
    const float* out_w = (const float*)d_in[5];
    const float* out_b = (const float*)d_in[6];

    float* xout = (float*)d_out;
    float* attn = xout + (size_t)BT * D_MODEL;

    static __nv_bfloat16 *p_hhi = nullptr, *p_hlo, *p_wqh, *p_wql, *p_woh, *p_wol, *p_aoh, *p_aol;
    static float* p_qkv;
    if (!p_hhi) {
        cudaGetSymbolAddress((void**)&p_hhi, g_h_hi);
        cudaGetSymbolAddress((void**)&p_hlo, g_h_lo);
        cudaGetSymbolAddress((void**)&p_wqh, g_wq_hi);
        cudaGetSymbolAddress((void**)&p_wql, g_wq_lo);
        cudaGetSymbolAddress((void**)&p_woh, g_wo_hi);
        cudaGetSymbolAddress((void**)&p_wol, g_wo_lo);
        cudaGetSymbolAddress((void**)&p_aoh, g_ao_hi);
        cudaGetSymbolAddress((void**)&p_aol, g_ao_lo);
        cudaGetSymbolAddress((void**)&p_qkv, g_qkv);
    }

    ln_kernel<<<BT, 256>>>(x, ln_g, ln_b, p_hhi, p_hlo);
    tsplit_kernel<<<dim3(QKV_N / 32, D_MODEL / 32), dim3(32, 8)>>>(qkv_w, p_wqh, p_wql, D_MODEL, QKV_N);
    tsplit_kernel<<<dim3(D_MODEL / 32, D_MODEL / 32), dim3(32, 8)>>>(out_w, p_woh, p_wol, D_MODEL, D_MODEL);

    gemm_mma<false><<<dim3(QKV_N / 128, BT / 128), 256>>>(
        p_hhi, p_hlo, p_wqh, p_wql, qkv_b, nullptr, p_qkv, QKV_N, D_MODEL);

    scores_kernel<<<dim3(32, 32, 32), 256>>>(p_qkv, attn);
    softmax_kernel<<<BATCH * NH * T, 256>>>(attn);
    av_kernel<<<dim3(32, 32), 256>>>(attn, p_qkv, p_aoh, p_aol);

    gemm_mma<true><<<dim3(D_MODEL / 128, BT / 128), 256>>>(
        p_aoh, p_aol, p_woh, p_wol, out_b, x, xout, D_MODEL, D_MODEL);
}

// round 6
// speedup vs baseline: 1.8602x; 1.4469x over previous
#include <cuda_runtime.h>
#include <cuda_bf16.h>
#include <cstdint>
#include <math.h>

#define D_MODEL 1024
#define NH      16
#define DH      64
#define BATCH   2
#define T       2048
#define BT      4096
#define QKV_N   3072

typedef __nv_bfloat16 bf16;
typedef __nv_bfloat162 bf162;

// ---------------------------------------------------------------------------
// Scratch
// ---------------------------------------------------------------------------
__device__ bf16 g_h_hi[(size_t)BT * D_MODEL];
__device__ bf16 g_h_lo[(size_t)BT * D_MODEL];
__device__ bf16 g_wq_hi[(size_t)QKV_N * D_MODEL];
__device__ bf16 g_wq_lo[(size_t)QKV_N * D_MODEL];
__device__ bf16 g_wo_hi[(size_t)D_MODEL * D_MODEL];
__device__ bf16 g_wo_lo[(size_t)D_MODEL * D_MODEL];
// q/k/v in [b*NH+h][T][64] layout, hi/lo split
__device__ bf16 g_q_hi[(size_t)32 * T * DH];
__device__ bf16 g_q_lo[(size_t)32 * T * DH];
__device__ bf16 g_k_hi[(size_t)32 * T * DH];
__device__ bf16 g_k_lo[(size_t)32 * T * DH];
__device__ bf16 g_v_hi[(size_t)32 * T * DH];
__device__ bf16 g_v_lo[(size_t)32 * T * DH];
__device__ bf16 g_ao_hi[(size_t)BT * D_MODEL];
__device__ bf16 g_ao_lo[(size_t)BT * D_MODEL];

// ---------------------------------------------------------------------------
// MMA helpers
// ---------------------------------------------------------------------------
__device__ __forceinline__ uint32_t smem_u32(const void* p) {
    uint32_t a;
    asm("{ .reg .u64 t; cvta.to.shared.u64 t, %1; cvt.u32.u64 %0, t; }" : "=r"(a) : "l"(p));
    return a;
}
#define LDSM4(r0, r1, r2, r3, addr)                                              \
    asm volatile("ldmatrix.sync.aligned.m8n8.x4.shared.b16 {%0,%1,%2,%3}, [%4];" \
                 : "=r"(r0), "=r"(r1), "=r"(r2), "=r"(r3) : "r"(addr))
#define LDSM4T(r0, r1, r2, r3, addr)                                                   \
    asm volatile("ldmatrix.sync.aligned.m8n8.x4.trans.shared.b16 {%0,%1,%2,%3}, [%4];" \
                 : "=r"(r0), "=r"(r1), "=r"(r2), "=r"(r3) : "r"(addr))
#define MMA16816(c, a, b0, b1)                                                   \
    asm volatile("mma.sync.aligned.m16n8k16.row.col.f32.bf16.bf16.f32 "          \
                 "{%0,%1,%2,%3}, {%4,%5,%6,%7}, {%8,%9}, {%0,%1,%2,%3};"         \
                 : "+f"((c)[0]), "+f"((c)[1]), "+f"((c)[2]), "+f"((c)[3])        \
                 : "r"((a)[0]), "r"((a)[1]), "r"((a)[2]), "r"((a)[3]),           \
                   "r"(b0), "r"(b1))

// ---------------------------------------------------------------------------
// LayerNorm -> bf16 hi/lo split
// ---------------------------------------------------------------------------
__global__ void ln_kernel(const float* __restrict__ x, const float* __restrict__ gam,
                          const float* __restrict__ bet,
                          bf16* __restrict__ ohi, bf16* __restrict__ olo) {
    int row = blockIdx.x;
    const float* xr = x + (size_t)row * D_MODEL;
    float v[4];
    float s = 0.f, s2 = 0.f;
#pragma unroll
    for (int i = 0; i < 4; i++) {
        v[i] = xr[threadIdx.x + i * 256];
        s += v[i]; s2 += v[i] * v[i];
    }
#pragma unroll
    for (int o = 16; o > 0; o >>= 1) {
        s  += __shfl_xor_sync(~0u, s, o);
        s2 += __shfl_xor_sync(~0u, s2, o);
    }
    __shared__ float rs[8], rs2[8];
    int wid = threadIdx.x >> 5, lid = threadIdx.x & 31;
    if (lid == 0) { rs[wid] = s; rs2[wid] = s2; }
    __syncthreads();
    s = 0.f; s2 = 0.f;
#pragma unroll
    for (int i = 0; i < 8; i++) { s += rs[i]; s2 += rs2[i]; }
    float mu  = s * (1.f / D_MODEL);
    float var = s2 * (1.f / D_MODEL) - mu * mu;
    float inv = rsqrtf(var + 1e-5f);
#pragma unroll
    for (int i = 0; i < 4; i++) {
        int c = threadIdx.x + i * 256;
        float y = (v[i] - mu) * inv * gam[c] + bet[c];
        bf16 h = __float2bfloat16(y);
        ohi[(size_t)row * D_MODEL + c] = h;
        olo[(size_t)row * D_MODEL + c] = __float2bfloat16(y - __bfloat162float(h));
    }
}

// ---------------------------------------------------------------------------
// Transpose + bf16 split: W[K][N] -> out[N][K]
// ---------------------------------------------------------------------------
__global__ void tsplit_kernel(const float* __restrict__ W,
                              bf16* __restrict__ hi, bf16* __restrict__ lo,
                              int K, int N) {
    __shared__ float t[32][33];
    int n0 = blockIdx.x * 32, k0 = blockIdx.y * 32;
    int tx = threadIdx.x, ty = threadIdx.y;
#pragma unroll
    for (int j = 0; j < 4; j++)
        t[ty + j * 8][tx] = W[(size_t)(k0 + ty + j * 8) * N + n0 + tx];
    __syncthreads();
#pragma unroll
    for (int j = 0; j < 4; j++) {
        float v = t[tx][ty + j * 8];
        size_t o = (size_t)(n0 + ty + j * 8) * K + k0 + tx;
        bf16 h = __float2bfloat16(v);
        hi[o] = h;
        lo[o] = __float2bfloat16(v - __bfloat162float(h));
    }
}

// ---------------------------------------------------------------------------
// HMMA bf16-split GEMM for QKV: epilogue scatters q/k/v into [bh][t][64]
// hi/lo split buffers. 128x128x32 tiles, 8 warps (4x2), warp tile 32x64.
// ---------------------------------------------------------------------------
#define SA 40

__global__ void __launch_bounds__(256) gemm_mma_qkv(
    const bf16* __restrict__ Ah, const bf16* __restrict__ Al,
    const bf16* __restrict__ Bh, const bf16* __restrict__ Bl,
    const float* __restrict__ bias,
    bf16* __restrict__ qhi, bf16* __restrict__ qlo,
    bf16* __restrict__ khi, bf16* __restrict__ klo,
    bf16* __restrict__ vhi, bf16* __restrict__ vlo) {
    const int K = D_MODEL;
    __shared__ __align__(16) bf16 sAh[128 * SA];
    __shared__ __align__(16) bf16 sAl[128 * SA];
    __shared__ __align__(16) bf16 sBh[128 * SA];
    __shared__ __align__(16) bf16 sBl[128 * SA];

    int tid = threadIdx.x;
    int wid = tid >> 5, lane = tid & 31;
    int wm = wid & 3, wn = wid >> 2;
    int bm = blockIdx.y, bn = blockIdx.x;

    uint32_t uAh = smem_u32(sAh), uAl = smem_u32(sAl);
    uint32_t uBh = smem_u32(sBh), uBl = smem_u32(sBl);

    int a_row = wm * 32 + ((lane >> 3) & 1) * 8 + (lane & 7);
    int a_kc  = (lane >> 4) * 8;
    int b_row = wn * 64 + (lane >> 4) * 8 + (lane & 7);
    int b_kc  = ((lane >> 3) & 1) * 8;

    float c[2][8][4];
#pragma unroll
    for (int i = 0; i < 2; i++)
#pragma unroll
        for (int j = 0; j < 8; j++)
#pragma unroll
            for (int q = 0; q < 4; q++) c[i][j][q] = 0.f;

    int ldr = tid >> 2, ldc = (tid & 3) * 8;

    for (int c0 = 0; c0 < K; c0 += 32) {
        __syncthreads();
#pragma unroll
        for (int it = 0; it < 2; it++) {
            int r = ldr + it * 64;
            size_t ga = (size_t)(bm * 128 + r) * K + c0 + ldc;
            size_t gb = (size_t)(bn * 128 + r) * K + c0 + ldc;
            int so = r * SA + ldc;
            *(uint4*)&sAh[so] = *(const uint4*)&Ah[ga];
            *(uint4*)&sAl[so] = *(const uint4*)&Al[ga];
            *(uint4*)&sBh[so] = *(const uint4*)&Bh[gb];
            *(uint4*)&sBl[so] = *(const uint4*)&Bl[gb];
        }
        __syncthreads();

#pragma unroll
        for (int ks = 0; ks < 2; ks++) {
            uint32_t ah[2][4], al[2][4], bh[4][4], bl[4][4];
#pragma unroll
            for (int ma = 0; ma < 2; ma++) {
                uint32_t off = ((a_row + ma * 16) * SA + a_kc + ks * 16) * 2;
                LDSM4(ah[ma][0], ah[ma][1], ah[ma][2], ah[ma][3], uAh + off);
                LDSM4(al[ma][0], al[ma][1], al[ma][2], al[ma][3], uAl + off);
            }
#pragma unroll
            for (int nb2 = 0; nb2 < 4; nb2++) {
                uint32_t off = ((b_row + nb2 * 16) * SA + b_kc + ks * 16) * 2;
                LDSM4(bh[nb2][0], bh[nb2][1], bh[nb2][2], bh[nb2][3], uBh + off);
                LDSM4(bl[nb2][0], bl[nb2][1], bl[nb2][2], bl[nb2][3], uBl + off);
            }
#pragma unroll
            for (int ma = 0; ma < 2; ma++)
#pragma unroll
                for (int nb = 0; nb < 8; nb++) {
                    int n2 = nb >> 1, o = (nb & 1) * 2;
                    MMA16816(c[ma][nb], ah[ma], bh[n2][o], bh[n2][o + 1]);
                    MMA16816(c[ma][nb], ah[ma], bl[n2][o], bl[n2][o + 1]);
                    MMA16816(c[ma][nb], al[ma], bh[n2][o], bh[n2][o + 1]);
                }
        }
    }

    // Epilogue: scatter into q/k/v split buffers
    int r0 = bm * 128 + wm * 32 + (lane >> 2);
#pragma unroll
    for (int ma = 0; ma < 2; ma++) {
#pragma unroll
        for (int nb = 0; nb < 8; nb++) {
            int col = bn * 128 + wn * 64 + nb * 8 + (lane & 3) * 2;
            int hg = col >> 6;              // global head 0..47
            int sec = hg >> 4;              // 0=q 1=k 2=v
            int h = hg & 15;
            int c64 = col & 63;
            bf16* dh = (sec == 0) ? qhi : (sec == 1) ? khi : vhi;
            bf16* dl = (sec == 0) ? qlo : (sec == 1) ? klo : vlo;
            float bx = bias[col], by = bias[col + 1];
#pragma unroll
            for (int half = 0; half < 2; half++) {
                int row = r0 + ma * 16 + half * 8;
                int t = row & (T - 1), b = row >> 11;
                size_t idx = (((size_t)(b * NH + h)) * T + t) * DH + c64;
                float y0 = c[ma][nb][half * 2 + 0] + bx;
                float y1 = c[ma][nb][half * 2 + 1] + by;
                bf16 h0 = __float2bfloat16(y0);
                bf16 h1 = __float2bfloat16(y1);
                bf162 hv; hv.x = h0; hv.y = h1;
                bf162 lv;
                lv.x = __float2bfloat16(y0 - __bfloat162float(h0));
                lv.y = __float2bfloat16(y1 - __bfloat162float(h1));
                *(bf162*)&dh[idx] = hv;
                *(bf162*)&dl[idx] = lv;
            }
        }
    }
}

// ---------------------------------------------------------------------------
// HMMA out-projection GEMM (fp32 epilogue + bias + residual)
// ---------------------------------------------------------------------------
__global__ void __launch_bounds__(256) gemm_mma_out(
    const bf16* __restrict__ Ah, const bf16* __restrict__ Al,
    const bf16* __restrict__ Bh, const bf16* __restrict__ Bl,
    const float* __restrict__ bias, const float* __restrict__ res,
    float* __restrict__ C) {
    const int N = D_MODEL, K = D_MODEL;
    __shared__ __align__(16) bf16 sAh[128 * SA];
    __shared__ __align__(16) bf16 sAl[128 * SA];
    __shared__ __align__(16) bf16 sBh[128 * SA];
    __shared__ __align__(16) bf16 sBl[128 * SA];

    int tid = threadIdx.x;
    int wid = tid >> 5, lane = tid & 31;
    int wm = wid & 3, wn = wid >> 2;
    int bm = blockIdx.y, bn = blockIdx.x;

    uint32_t uAh = smem_u32(sAh), uAl = smem_u32(sAl);
    uint32_t uBh = smem_u32(sBh), uBl = smem_u32(sBl);

    int a_row = wm * 32 + ((lane >> 3) & 1) * 8 + (lane & 7);
    int a_kc  = (lane >> 4) * 8;
    int b_row = wn * 64 + (lane >> 4) * 8 + (lane & 7);
    int b_kc  = ((lane >> 3) & 1) * 8;

    float c[2][8][4];
#pragma unroll
    for (int i = 0; i < 2; i++)
#pragma unroll
        for (int j = 0; j < 8; j++)
#pragma unroll
            for (int q = 0; q < 4; q++) c[i][j][q] = 0.f;

    int ldr = tid >> 2, ldc = (tid & 3) * 8;

    for (int c0 = 0; c0 < K; c0 += 32) {
        __syncthreads();
#pragma unroll
        for (int it = 0; it < 2; it++) {
            int r = ldr + it * 64;
            size_t ga = (size_t)(bm * 128 + r) * K + c0 + ldc;
            size_t gb = (size_t)(bn * 128 + r) * K + c0 + ldc;
            int so = r * SA + ldc;
            *(uint4*)&sAh[so] = *(const uint4*)&Ah[ga];
            *(uint4*)&sAl[so] = *(const uint4*)&Al[ga];
            *(uint4*)&sBh[so] = *(const uint4*)&Bh[gb];
            *(uint4*)&sBl[so] = *(const uint4*)&Bl[gb];
        }
        __syncthreads();

#pragma unroll
        for (int ks = 0; ks < 2; ks++) {
            uint32_t ah[2][4], al[2][4], bh[4][4], bl[4][4];
#pragma unroll
            for (int ma = 0; ma < 2; ma++) {
                uint32_t off = ((a_row + ma * 16) * SA + a_kc + ks * 16) * 2;
                LDSM4(ah[ma][0], ah[ma][1], ah[ma][2], ah[ma][3], uAh + off);
                LDSM4(al[ma][0], al[ma][1], al[ma][2], al[ma][3], uAl + off);
            }
#pragma unroll
            for (int nb2 = 0; nb2 < 4; nb2++) {
                uint32_t off = ((b_row + nb2 * 16) * SA + b_kc + ks * 16) * 2;
                LDSM4(bh[nb2][0], bh[nb2][1], bh[nb2][2], bh[nb2][3], uBh + off);
                LDSM4(bl[nb2][0], bl[nb2][1], bl[nb2][2], bl[nb2][3], uBl + off);
            }
#pragma unroll
            for (int ma = 0; ma < 2; ma++)
#pragma unroll
                for (int nb = 0; nb < 8; nb++) {
                    int n2 = nb >> 1, o = (nb & 1) * 2;
                    MMA16816(c[ma][nb], ah[ma], bh[n2][o], bh[n2][o + 1]);
                    MMA16816(c[ma][nb], ah[ma], bl[n2][o], bl[n2][o + 1]);
                    MMA16816(c[ma][nb], al[ma], bh[n2][o], bh[n2][o + 1]);
                }
        }
    }

    int r0 = bm * 128 + wm * 32 + (lane >> 2);
#pragma unroll
    for (int ma = 0; ma < 2; ma++) {
#pragma unroll
        for (int nb = 0; nb < 8; nb++) {
            int col = bn * 128 + wn * 64 + nb * 8 + (lane & 3) * 2;
            int ra = r0 + ma * 16, rb = ra + 8;
            float2 o0, o1;
            o0.x = c[ma][nb][0] + bias[col];
            o0.y = c[ma][nb][1] + bias[col + 1];
            o1.x = c[ma][nb][2] + bias[col];
            o1.y = c[ma][nb][3] + bias[col + 1];
            float2 r2a = *(const float2*)&res[(size_t)ra * N + col];
            float2 r2b = *(const float2*)&res[(size_t)rb * N + col];
            o0.x += r2a.x; o0.y += r2a.y;
            o1.x += r2b.x; o1.y += r2b.y;
            *(float2*)&C[(size_t)ra * N + col] = o0;
            *(float2*)&C[(size_t)rb * N + col] = o1;
        }
    }
}

// ---------------------------------------------------------------------------
// Scores via HMMA: S = (Qh+Ql)(Kh+Kl)^T / 8, causal. 128x128 tile per block.
// Upper-triangle tiles: zero fill. Dynamic smem: 4 tiles of 128x64 bf16 (pad 72).
// ---------------------------------------------------------------------------
#define SK 72
#define SCORES_SMEM (4 * 128 * SK * 2)

__global__ void __launch_bounds__(256) scores_mma(
    const bf16* __restrict__ qh, const bf16* __restrict__ ql,
    const bf16* __restrict__ kh, const bf16* __restrict__ kl,
    float* __restrict__ attn) {
    int kt = blockIdx.x, qt = blockIdx.y, bh = blockIdx.z;
    int tid = threadIdx.x;
    float* ablk = attn + ((size_t)bh * T + qt * 128) * T + kt * 128;

    if (kt > qt) {
        int r = tid >> 1, c0 = (tid & 1) * 64;
        float4 z = make_float4(0.f, 0.f, 0.f, 0.f);
#pragma unroll
        for (int j = 0; j < 16; j++)
            *(float4*)&ablk[(size_t)r * T + c0 + j * 4] = z;
        return;
    }

    extern __shared__ char dyn[];
    bf16* sQh = (bf16*)dyn;
    bf16* sQl = sQh + 128 * SK;
    bf16* sKh = sQl + 128 * SK;
    bf16* sKl = sKh + 128 * SK;

    const bf16* qhb = qh + ((size_t)bh * T + qt * 128) * DH;
    const bf16* qlb = ql + ((size_t)bh * T + qt * 128) * DH;
    const bf16* khb = kh + ((size_t)bh * T + kt * 128) * DH;
    const bf16* klb = kl + ((size_t)bh * T + kt * 128) * DH;

#pragma unroll
    for (int it = 0; it < 4; it++) {
        int idx = tid + it * 256;           // 0..1023
        int r = idx >> 3, cc = (idx & 7) * 8;
        int so = r * SK + cc;
        size_t go = (size_t)r * DH + cc;
        *(uint4*)&sQh[so] = *(const uint4*)&qhb[go];
        *(uint4*)&sQl[so] = *(const uint4*)&qlb[go];
        *(uint4*)&sKh[so] = *(const uint4*)&khb[go];
        *(uint4*)&sKl[so] = *(const uint4*)&klb[go];
    }
    __syncthreads();

    int wid = tid >> 5, lane = tid & 31;
    int wm = wid & 3, wn = wid >> 2;
    uint32_t uQh = smem_u32(sQh), uQl = smem_u32(sQl);
    uint32_t uKh = smem_u32(sKh), uKl = smem_u32(sKl);

    int a_row = wm * 32 + ((lane >> 3) & 1) * 8 + (lane & 7);
    int a_kc  = (lane >> 4) * 8;
    int b_row = wn * 64 + (lane >> 4) * 8 + (lane & 7);
    int b_kc  = ((lane >> 3) & 1) * 8;

    float c[2][8][4];
#pragma unroll
    for (int i = 0; i < 2; i++)
#pragma unroll
        for (int j = 0; j < 8; j++)
#pragma unroll
            for (int q = 0; q < 4; q++) c[i][j][q] = 0.f;

#pragma unroll
    for (int ks = 0; ks < 4; ks++) {
        uint32_t ah[2][4], al[2][4], bh2[4][4], bl2[4][4];
#pragma unroll
        for (int ma = 0; ma < 2; ma++) {
            uint32_t off = ((a_row + ma * 16) * SK + a_kc + ks * 16) * 2;
            LDSM4(ah[ma][0], ah[ma][1], ah[ma][2], ah[ma][3], uQh + off);
            LDSM4(al[ma][0], al[ma][1], al[ma][2], al[ma][3], uQl + off);
        }
#pragma unroll
        for (int nb2 = 0; nb2 < 4; nb2++) {
            uint32_t off = ((b_row + nb2 * 16) * SK + b_kc + ks * 16) * 2;
            LDSM4(bh2[nb2][0], bh2[nb2][1], bh2[nb2][2], bh2[nb2][3], uKh + off);
            LDSM4(bl2[nb2][0], bl2[nb2][1], bl2[nb2][2], bl2[nb2][3], uKl + off);
        }
#pragma unroll
        for (int ma = 0; ma < 2; ma++)
#pragma unroll
            for (int nb = 0; nb < 8; nb++) {
                int n2 = nb >> 1, o = (nb & 1) * 2;
                MMA16816(c[ma][nb], ah[ma], bh2[n2][o], bh2[n2][o + 1]);
                MMA16816(c[ma][nb], ah[ma], bl2[n2][o], bl2[n2][o + 1]);
                MMA16816(c[ma][nb], al[ma], bh2[n2][o], bh2[n2][o + 1]);
            }
    }

    bool diag = (qt == kt);
    int lr0 = wm * 32 + (lane >> 2);
#pragma unroll
    for (int ma = 0; ma < 2; ma++) {
#pragma unroll
        for (int nb = 0; nb < 8; nb++) {
            int colc = wn * 64 + nb * 8 + (lane & 3) * 2;
#pragma unroll
            for (int half = 0; half < 2; half++) {
                int lrow = lr0 + ma * 16 + half * 8;
                float2 o;
                o.x = c[ma][nb][half * 2 + 0] * 0.125f;
                o.y = c[ma][nb][half * 2 + 1] * 0.125f;
                if (diag) {
                    if (colc > lrow) o.x = 0.f;
                    if (colc + 1 > lrow) o.y = 0.f;
                }
                *(float2*)&ablk[(size_t)lrow * T + colc] = o;
            }
        }
    }
}

// ---------------------------------------------------------------------------
// Softmax (register-resident single pass)
// ---------------------------------------------------------------------------
__global__ void softmax_kernel(float* __restrict__ attn) {
    int row = blockIdx.x;
    int q = row & (T - 1);
    int n = q + 1;
    float* p = attn + (size_t)row * T;
    int tid = threadIdx.x;

    float v[8];
    float m = -1e30f;
#pragma unroll
    for (int j = 0; j < 8; j++) {
        int i = tid + j * 256;
        v[j] = (i < n) ? p[i] : -1e30f;
        m = fmaxf(m, v[j]);
    }
    __shared__ float smax[8], ssum[8];
    int wid = tid >> 5, lid = tid & 31;
#pragma unroll
    for (int o = 16; o > 0; o >>= 1) m = fmaxf(m, __shfl_xor_sync(~0u, m, o));
    if (lid == 0) smax[wid] = m;
    __syncthreads();
    m = smax[0];
#pragma unroll
    for (int i = 1; i < 8; i++) m = fmaxf(m, smax[i]);

    float s = 0.f;
#pragma unroll
    for (int j = 0; j < 8; j++) {
        v[j] = __expf(v[j] - m);
        s += v[j];
    }
#pragma unroll
    for (int o = 16; o > 0; o >>= 1) s += __shfl_xor_sync(~0u, s, o);
    if (lid == 0) ssum[wid] = s;
    __syncthreads();
    s = 0.f;
#pragma unroll
    for (int i = 0; i < 8; i++) s += ssum[i];
    float inv = 1.f / s;

#pragma unroll
    for (int j = 0; j < 8; j++) {
        int i = tid + j * 256;
        if (i < n) p[i] = v[j] * inv;
    }
}

// ---------------------------------------------------------------------------
// O = P @ V via HMMA. Per block: (qt, bh), O tile 128x64.
// P converted fp32->bf16 hi/lo in smem; V as B via ldmatrix.trans.
// ---------------------------------------------------------------------------
#define SP 136
#define SV 72
#define AV_SMEM (2 * 128 * SP * 2 + 2 * 128 * SV * 2)

__global__ void __launch_bounds__(256) av_mma(
    const float* __restrict__ attn,
    const bf16* __restrict__ vh, const bf16* __restrict__ vl,
    bf16* __restrict__ ohi, bf16* __restrict__ olo) {
    int qt = blockIdx.x, bh = blockIdx.y;
    int b = bh >> 4, h = bh & 15;
    int tid = threadIdx.x;
    int wid = tid >> 5, lane = tid & 31;
    int wm = wid & 3, wn = wid >> 2;         // O warp tile: 32 q x 32 d

    extern __shared__ char dyn[];
    bf16* sPh = (bf16*)dyn;
    bf16* sPl = sPh + 128 * SP;
    bf16* sVh = sPl + 128 * SP;
    bf16* sVl = sVh + 128 * SV;
    uint32_t uPh = smem_u32(sPh), uPl = smem_u32(sPl);
    uint32_t uVh = smem_u32(sVh), uVl = smem_u32(sVl);

    const float* arow = attn + ((size_t)bh * T + qt * 128) * T;
    const bf16* vhb = vh + (size_t)bh * T * DH;
    const bf16* vlb = vl + (size_t)bh * T * DH;

    float c[2][4][4];
#pragma unroll
    for (int i = 0; i < 2; i++)
#pragma unroll
        for (int j = 0; j < 4; j++)
#pragma unroll
            for (int q = 0; q < 4; q++) c[i][j][q] = 0.f;

    int pr = tid >> 1, pc0 = (tid & 1) * 64;

    int a_row = wm * 32 + ((lane >> 3) & 1) * 8 + (lane & 7);
    int a_kc  = (lane >> 4) * 8;
    int v_k   = lane & 15;
    int v_n   = (lane >> 4) * 8;

    for (int kt = 0; kt <= qt; kt++) {
        __syncthreads();
        // P tile: 128x128 fp32 -> bf16 split
        {
            const float* src = arow + (size_t)pr * T + kt * 128 + pc0;
            int so = pr * SP + pc0;
#pragma unroll
            for (int j = 0; j < 16; j++) {
                float4 vv = *(const float4*)&src[j * 4];
                bf162 h0, h1, l0, l1;
                h0.x = __float2bfloat16(vv.x); h0.y = __float2bfloat16(vv.y);
                h1.x = __float2bfloat16(vv.z); h1.y = __float2bfloat16(vv.w);
                l0.x = __float2bfloat16(vv.x - __bfloat162float(h0.x));
                l0.y = __float2bfloat16(vv.y - __bfloat162float(h0.y));
                l1.x = __float2bfloat16(vv.z - __bfloat162float(h1.x));
                l1.y = __float2bfloat16(vv.w - __bfloat162float(h1.y));
                *(bf162*)&sPh[so + j * 4]     = h0;
                *(bf162*)&sPh[so + j * 4 + 2] = h1;
                *(bf162*)&sPl[so + j * 4]     = l0;
                *(bf162*)&sPl[so + j * 4 + 2] = l1;
            }
        }
        // V tile: 128 tokens x 64
#pragma unroll
        for (int it = 0; it < 4; it++) {
            int idx = tid + it * 256;
            int r = idx >> 3, cc = (idx & 7) * 8;
            size_t go = (size_t)(kt * 128 + r) * DH + cc;
            *(uint4*)&sVh[r * SV + cc] = *(const uint4*)&vhb[go];
            *(uint4*)&sVl[r * SV + cc] = *(const uint4*)&vlb[go];
        }
        __syncthreads();

#pragma unroll
        for (int ks = 0; ks < 8; ks++) {
            uint32_t ah[2][4], al[2][4], bh2[2][4], bl2[2][4];
#pragma unroll
            for (int ma = 0; ma < 2; ma++) {
                uint32_t off = ((a_row + ma * 16) * SP + a_kc + ks * 16) * 2;
                LDSM4(ah[ma][0], ah[ma][1], ah[ma][2], ah[ma][3], uPh + off);
                LDSM4(al[ma][0], al[ma][1], al[ma][2], al[ma][3], uPl + off);
            }
#pragma unroll
            for (int n16 = 0; n16 < 2; n16++) {
                uint32_t off = ((ks * 16 + v_k) * SV + wn * 32 + n16 * 16 + v_n) * 2;
                LDSM4T(bh2[n16][0], bh2[n16][1], bh2[n16][2], bh2[n16][3], uVh + off);
                LDSM4T(bl2[n16][0], bl2[n16][1], bl2[n16][2], bl2[n16][3], uVl + off);
            }
#pragma unroll
            for (int ma = 0; ma < 2; ma++)
#pragma unroll
                for (int nb = 0; nb < 4; nb++) {
                    int n2 = nb >> 1, o = (nb & 1) * 2;
                    MMA16816(c[ma][nb], ah[ma], bh2[n2][o], bh2[n2][o + 1]);
                    MMA16816(c[ma][nb], ah[ma], bl2[n2][o], bl2[n2][o + 1]);
                    MMA16816(c[ma][nb], al[ma], bh2[n2][o], bh2[n2][o + 1]);
                }
        }
    }

    // Epilogue: write O as bf16 hi/lo into [token][D_MODEL] with head offset
    int t0 = qt * 128 + wm * 32 + (lane >> 2);
#pragma unroll
    for (int ma = 0; ma < 2; ma++) {
#pragma unroll
        for (int nb = 0; nb < 4; nb++) {
            int d = wn * 32 + nb * 8 + (lane & 3) * 2;
#pragma unroll
            for (int half = 0; half < 2; half++) {
                int t = t0 + ma * 16 + half * 8;
                size_t idx = ((size_t)(b * T + t)) * D_MODEL + h * DH + d;
                float y0 = c[ma][nb][half * 2 + 0];
                float y1 = c[ma][nb][half * 2 + 1];
                bf16 h0 = __float2bfloat16(y0);
                bf16 h1 = __float2bfloat16(y1);
                bf162 hv; hv.x = h0; hv.y = h1;
                bf162 lv;
                lv.x = __float2bfloat16(y0 - __bfloat162float(h0));
                lv.y = __float2bfloat16(y1 - __bfloat162float(h1));
                *(bf162*)&ohi[idx] = hv;
                *(bf162*)&olo[idx] = lv;
            }
        }
    }
}

// ---------------------------------------------------------------------------
extern "C" void kernel_launch(void* const* d_in, const int* in_sizes, int n_in,
                              void* d_out, int out_size) {
    (void)in_sizes; (void)n_in; (void)out_size;
    const float* x     = (const float*)d_in[0];
    const float* ln_g  = (const float*)d_in[1];
    const float* ln_b  = (const float*)d_in[2];
    const float* qkv_w = (const float*)d_in[3];
    const float* qkv_b = (const float*)d_in[4];
    const float* out_w = (const float*)d_in[5];
    const float* out_b = (const float*)d_in[6];

    float* xout = (float*)d_out;
    float* attn = xout + (size_t)BT * D_MODEL;

    static bf16 *p_hhi = nullptr, *p_hlo, *p_wqh, *p_wql, *p_woh, *p_wol;
    static bf16 *p_qh, *p_ql, *p_kh, *p_kl, *p_vh, *p_vl, *p_aoh, *p_aol;
    if (!p_hhi) {
        cudaGetSymbolAddress((void**)&p_hhi, g_h_hi);
        cudaGetSymbolAddress((void**)&p_hlo, g_h_lo);
        cudaGetSymbolAddress((void**)&p_wqh, g_wq_hi);
        cudaGetSymbolAddress((void**)&p_wql, g_wq_lo);
        cudaGetSymbolAddress((void**)&p_woh, g_wo_hi);
        cudaGetSymbolAddress((void**)&p_wol, g_wo_lo);
        cudaGetSymbolAddress((void**)&p_qh, g_q_hi);
        cudaGetSymbolAddress((void**)&p_ql, g_q_lo);
        cudaGetSymbolAddress((void**)&p_kh, g_k_hi);
        cudaGetSymbolAddress((void**)&p_kl, g_k_lo);
        cudaGetSymbolAddress((void**)&p_vh, g_v_hi);
        cudaGetSymbolAddress((void**)&p_vl, g_v_lo);
        cudaGetSymbolAddress((void**)&p_aoh, g_ao_hi);
        cudaGetSymbolAddress((void**)&p_aol, g_ao_lo);
        cudaFuncSetAttribute(scores_mma, cudaFuncAttributeMaxDynamicSharedMemorySize, SCORES_SMEM);
        cudaFuncSetAttribute(av_mma, cudaFuncAttributeMaxDynamicSharedMemorySize, AV_SMEM);
    }

    ln_kernel<<<BT, 256>>>(x, ln_g, ln_b, p_hhi, p_hlo);
    tsplit_kernel<<<dim3(QKV_N / 32, D_MODEL / 32), dim3(32, 8)>>>(qkv_w, p_wqh, p_wql, D_MODEL, QKV_N);
    tsplit_kernel<<<dim3(D_MODEL / 32, D_MODEL / 32), dim3(32, 8)>>>(out_w, p_woh, p_wol, D_MODEL, D_MODEL);

    gemm_mma_qkv<<<dim3(QKV_N / 128, BT / 128), 256>>>(
        p_hhi, p_hlo, p_wqh, p_wql, qkv_b, p_qh, p_ql, p_kh, p_kl, p_vh, p_vl);

    scores_mma<<<dim3(16, 16, 32), 256, SCORES_SMEM>>>(p_qh, p_ql, p_kh, p_kl, attn);
    softmax_kernel<<<BATCH * NH * T, 256>>>(attn);
    av_mma<<<dim3(16, 32), 256, AV_SMEM>>>(attn, p_vh, p_vl, p_aoh, p_aol);

    gemm_mma_out<<<dim3(D_MODEL / 128, BT / 128), 256>>>(
        p_aoh, p_aol, p_woh, p_wol, out_b, x, xout);
}

// round 7
// speedup vs baseline: 2.2332x; 1.2005x over previous
#include <cuda_runtime.h>
#include <cuda_bf16.h>
#include <cstdint>
#include <math.h>

#define D_MODEL 1024
#define NH      16
#define DH      64
#define BATCH   2
#define T       2048
#define BT      4096
#define QKV_N   3072

typedef __nv_bfloat16 bf16;
typedef __nv_bfloat162 bf162;

// ---------------------------------------------------------------------------
// Scratch
// ---------------------------------------------------------------------------
__device__ bf16 g_h_hi[(size_t)BT * D_MODEL];
__device__ bf16 g_h_lo[(size_t)BT * D_MODEL];
__device__ bf16 g_wq_hi[(size_t)QKV_N * D_MODEL];
__device__ bf16 g_wq_lo[(size_t)QKV_N * D_MODEL];
__device__ bf16 g_wo_hi[(size_t)D_MODEL * D_MODEL];
__device__ bf16 g_wo_lo[(size_t)D_MODEL * D_MODEL];
__device__ bf16 g_q_hi[(size_t)32 * T * DH];
__device__ bf16 g_q_lo[(size_t)32 * T * DH];
__device__ bf16 g_k_hi[(size_t)32 * T * DH];
__device__ bf16 g_k_lo[(size_t)32 * T * DH];
__device__ bf16 g_v_hi[(size_t)32 * T * DH];
__device__ bf16 g_v_lo[(size_t)32 * T * DH];
__device__ bf16 g_ao_hi[(size_t)BT * D_MODEL];
__device__ bf16 g_ao_lo[(size_t)BT * D_MODEL];
// P (post-softmax) in bf16 hi/lo, [bh][q][T]
__device__ bf16 g_p_hi[(size_t)32 * T * T];
__device__ bf16 g_p_lo[(size_t)32 * T * T];

// ---------------------------------------------------------------------------
// Helpers
// ---------------------------------------------------------------------------
__device__ __forceinline__ uint32_t smem_u32(const void* p) {
    uint32_t a;
    asm("{ .reg .u64 t; cvta.to.shared.u64 t, %1; cvt.u32.u64 %0, t; }" : "=r"(a) : "l"(p));
    return a;
}
__device__ __forceinline__ void cp16(uint32_t dst, const void* src) {
    asm volatile("cp.async.cg.shared.global [%0], [%1], 16;" :: "r"(dst), "l"(src));
}
#define CP_COMMIT() asm volatile("cp.async.commit_group;" ::: "memory")
#define CP_WAIT0()  asm volatile("cp.async.wait_group 0;" ::: "memory")
#define CP_WAIT1()  asm volatile("cp.async.wait_group 1;" ::: "memory")
#define LDSM4(r0, r1, r2, r3, addr)                                              \
    asm volatile("ldmatrix.sync.aligned.m8n8.x4.shared.b16 {%0,%1,%2,%3}, [%4];" \
                 : "=r"(r0), "=r"(r1), "=r"(r2), "=r"(r3) : "r"(addr))
#define LDSM4T(r0, r1, r2, r3, addr)                                                   \
    asm volatile("ldmatrix.sync.aligned.m8n8.x4.trans.shared.b16 {%0,%1,%2,%3}, [%4];" \
                 : "=r"(r0), "=r"(r1), "=r"(r2), "=r"(r3) : "r"(addr))
#define MMA16816(c, a, b0, b1)                                                   \
    asm volatile("mma.sync.aligned.m16n8k16.row.col.f32.bf16.bf16.f32 "          \
                 "{%0,%1,%2,%3}, {%4,%5,%6,%7}, {%8,%9}, {%0,%1,%2,%3};"         \
                 : "+f"((c)[0]), "+f"((c)[1]), "+f"((c)[2]), "+f"((c)[3])        \
                 : "r"((a)[0]), "r"((a)[1]), "r"((a)[2]), "r"((a)[3]),           \
                   "r"(b0), "r"(b1))

// ---------------------------------------------------------------------------
// LayerNorm -> bf16 hi/lo split
// ---------------------------------------------------------------------------
__global__ void ln_kernel(const float* __restrict__ x, const float* __restrict__ gam,
                          const float* __restrict__ bet,
                          bf16* __restrict__ ohi, bf16* __restrict__ olo) {
    int row = blockIdx.x;
    const float* xr = x + (size_t)row * D_MODEL;
    float v[4];
    float s = 0.f, s2 = 0.f;
#pragma unroll
    for (int i = 0; i < 4; i++) {
        v[i] = xr[threadIdx.x + i * 256];
        s += v[i]; s2 += v[i] * v[i];
    }
#pragma unroll
    for (int o = 16; o > 0; o >>= 1) {
        s  += __shfl_xor_sync(~0u, s, o);
        s2 += __shfl_xor_sync(~0u, s2, o);
    }
    __shared__ float rs[8], rs2[8];
    int wid = threadIdx.x >> 5, lid = threadIdx.x & 31;
    if (lid == 0) { rs[wid] = s; rs2[wid] = s2; }
    __syncthreads();
    s = 0.f; s2 = 0.f;
#pragma unroll
    for (int i = 0; i < 8; i++) { s += rs[i]; s2 += rs2[i]; }
    float mu  = s * (1.f / D_MODEL);
    float var = s2 * (1.f / D_MODEL) - mu * mu;
    float inv = rsqrtf(var + 1e-5f);
#pragma unroll
    for (int i = 0; i < 4; i++) {
        int c = threadIdx.x + i * 256;
        float y = (v[i] - mu) * inv * gam[c] + bet[c];
        bf16 h = __float2bfloat16(y);
        ohi[(size_t)row * D_MODEL + c] = h;
        olo[(size_t)row * D_MODEL + c] = __float2bfloat16(y - __bfloat162float(h));
    }
}

// ---------------------------------------------------------------------------
// Transpose + bf16 split: W[K][N] -> out[N][K]
// ---------------------------------------------------------------------------
__global__ void tsplit_kernel(const float* __restrict__ W,
                              bf16* __restrict__ hi, bf16* __restrict__ lo,
                              int K, int N) {
    __shared__ float t[32][33];
    int n0 = blockIdx.x * 32, k0 = blockIdx.y * 32;
    int tx = threadIdx.x, ty = threadIdx.y;
#pragma unroll
    for (int j = 0; j < 4; j++)
        t[ty + j * 8][tx] = W[(size_t)(k0 + ty + j * 8) * N + n0 + tx];
    __syncthreads();
#pragma unroll
    for (int j = 0; j < 4; j++) {
        float v = t[tx][ty + j * 8];
        size_t o = (size_t)(n0 + ty + j * 8) * K + k0 + tx;
        bf16 h = __float2bfloat16(v);
        hi[o] = h;
        lo[o] = __float2bfloat16(v - __bfloat162float(h));
    }
}

// ---------------------------------------------------------------------------
// Pipelined HMMA GEMM pieces (2-stage cp.async), tiles 128x128x32
// ---------------------------------------------------------------------------
#define SA 40
#define GT_TILE2  (128 * SA * 2)          // bytes per tile
#define GT_STG2   (4 * GT_TILE2)          // bytes per stage
#define GEMM_SMEM (2 * GT_STG2)           // 81920

__device__ __forceinline__ void gemm_issue(
    uint32_t sb, int st, int kc, int bm, int bn, int tid, int K,
    const bf16* __restrict__ Ah, const bf16* __restrict__ Al,
    const bf16* __restrict__ Bh, const bf16* __restrict__ Bl) {
    int r = tid >> 2, cc = (tid & 3) * 8;
    int c0 = kc * 32;
    uint32_t base = sb + (uint32_t)st * GT_STG2;
#pragma unroll
    for (int it = 0; it < 2; it++) {
        int rr = r + it * 64;
        size_t ga = (size_t)(bm * 128 + rr) * K + c0 + cc;
        size_t gb = (size_t)(bn * 128 + rr) * K + c0 + cc;
        uint32_t so = (uint32_t)(rr * SA + cc) * 2;
        cp16(base + so, Ah + ga);
        cp16(base + GT_TILE2 + so, Al + ga);
        cp16(base + 2 * GT_TILE2 + so, Bh + gb);
        cp16(base + 3 * GT_TILE2 + so, Bl + gb);
    }
    CP_COMMIT();
}

// Mainloop body shared by both GEMMs (macro to keep accumulators in regs)
#define GEMM_MAINLOOP(K_)                                                        \
    int a_row = wm * 32 + ((lane >> 3) & 1) * 8 + (lane & 7);                    \
    int a_kc  = (lane >> 4) * 8;                                                 \
    int b_row = wn * 64 + (lane >> 4) * 8 + (lane & 7);                          \
    int b_kc  = ((lane >> 3) & 1) * 8;                                           \
    float c[2][8][4];                                                            \
    _Pragma("unroll") for (int i = 0; i < 2; i++)                                \
    _Pragma("unroll") for (int j = 0; j < 8; j++)                                \
    _Pragma("unroll") for (int q = 0; q < 4; q++) c[i][j][q] = 0.f;              \
    const int NK = (K_) / 32;                                                    \
    gemm_issue(sb, 0, 0, bm, bn, tid, (K_), Ah, Al, Bh, Bl);                     \
    for (int kc = 0; kc < NK; kc++) {                                            \
        if (kc + 1 < NK) { gemm_issue(sb, (kc + 1) & 1, kc + 1, bm, bn, tid,     \
                                      (K_), Ah, Al, Bh, Bl); CP_WAIT1(); }       \
        else CP_WAIT0();                                                         \
        __syncthreads();                                                         \
        uint32_t uAh = sb + (kc & 1) * GT_STG2;                                  \
        uint32_t uAl = uAh + GT_TILE2;                                           \
        uint32_t uBh = uAh + 2 * GT_TILE2;                                       \
        uint32_t uBl = uAh + 3 * GT_TILE2;                                       \
        _Pragma("unroll")                                                        \
        for (int ks = 0; ks < 2; ks++) {                                         \
            uint32_t ah[2][4], al[2][4], bh[4][4], bl[4][4];                     \
            _Pragma("unroll")                                                    \
            for (int ma = 0; ma < 2; ma++) {                                     \
                uint32_t off = ((a_row + ma * 16) * SA + a_kc + ks * 16) * 2;    \
                LDSM4(ah[ma][0], ah[ma][1], ah[ma][2], ah[ma][3], uAh + off);    \
                LDSM4(al[ma][0], al[ma][1], al[ma][2], al[ma][3], uAl + off);    \
            }                                                                    \
            _Pragma("unroll")                                                    \
            for (int nb2 = 0; nb2 < 4; nb2++) {                                  \
                uint32_t off = ((b_row + nb2 * 16) * SA + b_kc + ks * 16) * 2;   \
                LDSM4(bh[nb2][0], bh[nb2][1], bh[nb2][2], bh[nb2][3], uBh + off);\
                LDSM4(bl[nb2][0], bl[nb2][1], bl[nb2][2], bl[nb2][3], uBl + off);\
            }                                                                    \
            _Pragma("unroll")                                                    \
            for (int ma = 0; ma < 2; ma++)                                       \
            _Pragma("unroll")                                                    \
            for (int nb = 0; nb < 8; nb++) {                                     \
                int n2 = nb >> 1, o = (nb & 1) * 2;                              \
                MMA16816(c[ma][nb], ah[ma], bh[n2][o], bh[n2][o + 1]);           \
                MMA16816(c[ma][nb], ah[ma], bl[n2][o], bl[n2][o + 1]);           \
                MMA16816(c[ma][nb], al[ma], bh[n2][o], bh[n2][o + 1]);           \
            }                                                                    \
        }                                                                        \
        __syncthreads();                                                         \
    }

__global__ void __launch_bounds__(256) gemm_mma_qkv(
    const bf16* __restrict__ Ah, const bf16* __restrict__ Al,
    const bf16* __restrict__ Bh, const bf16* __restrict__ Bl,
    const float* __restrict__ bias,
    bf16* __restrict__ qhi, bf16* __restrict__ qlo,
    bf16* __restrict__ khi, bf16* __restrict__ klo,
    bf16* __restrict__ vhi, bf16* __restrict__ vlo) {
    extern __shared__ char dyn[];
    uint32_t sb = smem_u32(dyn);
    int tid = threadIdx.x;
    int wid = tid >> 5, lane = tid & 31;
    int wm = wid & 3, wn = wid >> 2;
    int bm = blockIdx.y, bn = blockIdx.x;

    GEMM_MAINLOOP(D_MODEL)

    // Epilogue: scatter into q/k/v split buffers
    int r0 = bm * 128 + wm * 32 + (lane >> 2);
#pragma unroll
    for (int ma = 0; ma < 2; ma++) {
#pragma unroll
        for (int nb = 0; nb < 8; nb++) {
            int col = bn * 128 + wn * 64 + nb * 8 + (lane & 3) * 2;
            int hg = col >> 6;
            int sec = hg >> 4;
            int h = hg & 15;
            int c64 = col & 63;
            bf16* dh = (sec == 0) ? qhi : (sec == 1) ? khi : vhi;
            bf16* dl = (sec == 0) ? qlo : (sec == 1) ? klo : vlo;
            float bx = bias[col], by = bias[col + 1];
#pragma unroll
            for (int half = 0; half < 2; half++) {
                int row = r0 + ma * 16 + half * 8;
                int t = row & (T - 1), b = row >> 11;
                size_t idx = (((size_t)(b * NH + h)) * T + t) * DH + c64;
                float y0 = c[ma][nb][half * 2 + 0] + bx;
                float y1 = c[ma][nb][half * 2 + 1] + by;
                bf16 h0 = __float2bfloat16(y0);
                bf16 h1 = __float2bfloat16(y1);
                bf162 hv; hv.x = h0; hv.y = h1;
                bf162 lv;
                lv.x = __float2bfloat16(y0 - __bfloat162float(h0));
                lv.y = __float2bfloat16(y1 - __bfloat162float(h1));
                *(bf162*)&dh[idx] = hv;
                *(bf162*)&dl[idx] = lv;
            }
        }
    }
}

__global__ void __launch_bounds__(256) gemm_mma_out(
    const bf16* __restrict__ Ah, const bf16* __restrict__ Al,
    const bf16* __restrict__ Bh, const bf16* __restrict__ Bl,
    const float* __restrict__ bias, const float* __restrict__ res,
    float* __restrict__ C) {
    const int N = D_MODEL;
    extern __shared__ char dyn[];
    uint32_t sb = smem_u32(dyn);
    int tid = threadIdx.x;
    int wid = tid >> 5, lane = tid & 31;
    int wm = wid & 3, wn = wid >> 2;
    int bm = blockIdx.y, bn = blockIdx.x;

    GEMM_MAINLOOP(D_MODEL)

    int r0 = bm * 128 + wm * 32 + (lane >> 2);
#pragma unroll
    for (int ma = 0; ma < 2; ma++) {
#pragma unroll
        for (int nb = 0; nb < 8; nb++) {
            int col = bn * 128 + wn * 64 + nb * 8 + (lane & 3) * 2;
            int ra = r0 + ma * 16, rb = ra + 8;
            float2 o0, o1;
            o0.x = c[ma][nb][0] + bias[col];
            o0.y = c[ma][nb][1] + bias[col + 1];
            o1.x = c[ma][nb][2] + bias[col];
            o1.y = c[ma][nb][3] + bias[col + 1];
            float2 r2a = *(const float2*)&res[(size_t)ra * N + col];
            float2 r2b = *(const float2*)&res[(size_t)rb * N + col];
            o0.x += r2a.x; o0.y += r2a.y;
            o1.x += r2b.x; o1.y += r2b.y;
            *(float2*)&C[(size_t)ra * N + col] = o0;
            *(float2*)&C[(size_t)rb * N + col] = o1;
        }
    }
}

// ---------------------------------------------------------------------------
// Scores via HMMA (unchanged from passing R6)
// ---------------------------------------------------------------------------
#define SK 72
#define SCORES_SMEM (4 * 128 * SK * 2)

__global__ void __launch_bounds__(256) scores_mma(
    const bf16* __restrict__ qh, const bf16* __restrict__ ql,
    const bf16* __restrict__ kh, const bf16* __restrict__ kl,
    float* __restrict__ attn) {
    int kt = blockIdx.x, qt = blockIdx.y, bh = blockIdx.z;
    int tid = threadIdx.x;
    float* ablk = attn + ((size_t)bh * T + qt * 128) * T + kt * 128;

    if (kt > qt) {
        int r = tid >> 1, c0 = (tid & 1) * 64;
        float4 z = make_float4(0.f, 0.f, 0.f, 0.f);
#pragma unroll
        for (int j = 0; j < 16; j++)
            *(float4*)&ablk[(size_t)r * T + c0 + j * 4] = z;
        return;
    }

    extern __shared__ char dyn[];
    bf16* sQh = (bf16*)dyn;
    bf16* sQl = sQh + 128 * SK;
    bf16* sKh = sQl + 128 * SK;
    bf16* sKl = sKh + 128 * SK;

    const bf16* qhb = qh + ((size_t)bh * T + qt * 128) * DH;
    const bf16* qlb = ql + ((size_t)bh * T + qt * 128) * DH;
    const bf16* khb = kh + ((size_t)bh * T + kt * 128) * DH;
    const bf16* klb = kl + ((size_t)bh * T + kt * 128) * DH;

#pragma unroll
    for (int it = 0; it < 4; it++) {
        int idx = tid + it * 256;
        int r = idx >> 3, cc = (idx & 7) * 8;
        int so = r * SK + cc;
        size_t go = (size_t)r * DH + cc;
        *(uint4*)&sQh[so] = *(const uint4*)&qhb[go];
        *(uint4*)&sQl[so] = *(const uint4*)&qlb[go];
        *(uint4*)&sKh[so] = *(const uint4*)&khb[go];
        *(uint4*)&sKl[so] = *(const uint4*)&klb[go];
    }
    __syncthreads();

    int wid = tid >> 5, lane = tid & 31;
    int wm = wid & 3, wn = wid >> 2;
    uint32_t uQh = smem_u32(sQh), uQl = smem_u32(sQl);
    uint32_t uKh = smem_u32(sKh), uKl = smem_u32(sKl);

    int a_row = wm * 32 + ((lane >> 3) & 1) * 8 + (lane & 7);
    int a_kc  = (lane >> 4) * 8;
    int b_row = wn * 64 + (lane >> 4) * 8 + (lane & 7);
    int b_kc  = ((lane >> 3) & 1) * 8;

    float c[2][8][4];
#pragma unroll
    for (int i = 0; i < 2; i++)
#pragma unroll
        for (int j = 0; j < 8; j++)
#pragma unroll
            for (int q = 0; q < 4; q++) c[i][j][q] = 0.f;

#pragma unroll
    for (int ks = 0; ks < 4; ks++) {
        uint32_t ah[2][4], al[2][4], bh2[4][4], bl2[4][4];
#pragma unroll
        for (int ma = 0; ma < 2; ma++) {
            uint32_t off = ((a_row + ma * 16) * SK + a_kc + ks * 16) * 2;
            LDSM4(ah[ma][0], ah[ma][1], ah[ma][2], ah[ma][3], uQh + off);
            LDSM4(al[ma][0], al[ma][1], al[ma][2], al[ma][3], uQl + off);
        }
#pragma unroll
        for (int nb2 = 0; nb2 < 4; nb2++) {
            uint32_t off = ((b_row + nb2 * 16) * SK + b_kc + ks * 16) * 2;
            LDSM4(bh2[nb2][0], bh2[nb2][1], bh2[nb2][2], bh2[nb2][3], uKh + off);
            LDSM4(bl2[nb2][0], bl2[nb2][1], bl2[nb2][2], bl2[nb2][3], uKl + off);
        }
#pragma unroll
        for (int ma = 0; ma < 2; ma++)
#pragma unroll
            for (int nb = 0; nb < 8; nb++) {
                int n2 = nb >> 1, o = (nb & 1) * 2;
                MMA16816(c[ma][nb], ah[ma], bh2[n2][o], bh2[n2][o + 1]);
                MMA16816(c[ma][nb], ah[ma], bl2[n2][o], bl2[n2][o + 1]);
                MMA16816(c[ma][nb], al[ma], bh2[n2][o], bh2[n2][o + 1]);
            }
    }

    bool diag = (qt == kt);
    int lr0 = wm * 32 + (lane >> 2);
#pragma unroll
    for (int ma = 0; ma < 2; ma++) {
#pragma unroll
        for (int nb = 0; nb < 8; nb++) {
            int colc = wn * 64 + nb * 8 + (lane & 3) * 2;
#pragma unroll
            for (int half = 0; half < 2; half++) {
                int lrow = lr0 + ma * 16 + half * 8;
                float2 o;
                o.x = c[ma][nb][half * 2 + 0] * 0.125f;
                o.y = c[ma][nb][half * 2 + 1] * 0.125f;
                if (diag) {
                    if (colc > lrow) o.x = 0.f;
                    if (colc + 1 > lrow) o.y = 0.f;
                }
                *(float2*)&ablk[(size_t)lrow * T + colc] = o;
            }
        }
    }
}

// ---------------------------------------------------------------------------
// Softmax: register-resident; writes fp32 P (output) + bf16 hi/lo P for av.
// bf16 buffers are zero-filled up to the row's 128-aligned boundary.
// ---------------------------------------------------------------------------
__global__ void softmax_kernel(float* __restrict__ attn,
                               bf16* __restrict__ phA, bf16* __restrict__ plA) {
    int row = blockIdx.x;
    int q = row & (T - 1);
    int n = q + 1;
    int nceil = (n + 127) & ~127;
    float* p = attn + (size_t)row * T;
    bf16* ph = phA + (size_t)row * T;
    bf16* pl = plA + (size_t)row * T;
    int tid = threadIdx.x;

    float v[8];
    float m = -1e30f;
#pragma unroll
    for (int j = 0; j < 8; j++) {
        int i = tid + j * 256;
        v[j] = (i < n) ? p[i] : -1e30f;
        m = fmaxf(m, v[j]);
    }
    __shared__ float smax[8], ssum[8];
    int wid = tid >> 5, lid = tid & 31;
#pragma unroll
    for (int o = 16; o > 0; o >>= 1) m = fmaxf(m, __shfl_xor_sync(~0u, m, o));
    if (lid == 0) smax[wid] = m;
    __syncthreads();
    m = smax[0];
#pragma unroll
    for (int i = 1; i < 8; i++) m = fmaxf(m, smax[i]);

    float s = 0.f;
#pragma unroll
    for (int j = 0; j < 8; j++) {
        v[j] = __expf(v[j] - m);     // invalid slots underflow to 0
        s += v[j];
    }
#pragma unroll
    for (int o = 16; o > 0; o >>= 1) s += __shfl_xor_sync(~0u, s, o);
    if (lid == 0) ssum[wid] = s;
    __syncthreads();
    s = 0.f;
#pragma unroll
    for (int i = 0; i < 8; i++) s += ssum[i];
    float inv = 1.f / s;

#pragma unroll
    for (int j = 0; j < 8; j++) {
        int i = tid + j * 256;
        float y = v[j] * inv;
        if (i < n) p[i] = y;
        if (i < nceil) {
            if (i >= n) y = 0.f;
            bf16 h = __float2bfloat16(y);
            ph[i] = h;
            pl[i] = __float2bfloat16(y - __bfloat162float(h));
        }
    }
}

// ---------------------------------------------------------------------------
// O = P @ V: 2-stage cp.async GEMM over 64-wide k tiles.
// A = P hi/lo bf16 (row stride T), B = V hi/lo via ldmatrix.trans.
// ---------------------------------------------------------------------------
#define SPK 72
#define SV  72
#define AV_PT2  (128 * SPK * 2)
#define AV_VT2  (64 * SV * 2)
#define AV_STG2 (2 * AV_PT2 + 2 * AV_VT2)
#define AV_SMEM (2 * AV_STG2)             // 110592

__device__ __forceinline__ void av_issue(
    uint32_t sb, int st, int kt, int qt, int tid,
    const bf16* __restrict__ ph, const bf16* __restrict__ pl,
    const bf16* __restrict__ vh, const bf16* __restrict__ vl) {
    uint32_t base = sb + (uint32_t)st * AV_STG2;
#pragma unroll
    for (int p = 0; p < 4; p++) {
        int idx = tid + p * 256;
        int r = idx >> 3, cc = (idx & 7) * 8;
        size_t g = (size_t)(qt * 128 + r) * T + kt * 64 + cc;
        uint32_t so = (uint32_t)(r * SPK + cc) * 2;
        cp16(base + so, ph + g);
        cp16(base + AV_PT2 + so, pl + g);
    }
#pragma unroll
    for (int p = 0; p < 2; p++) {
        int idx = tid + p * 256;
        int r = idx >> 3, cc = (idx & 7) * 8;
        size_t g = (size_t)(kt * 64 + r) * DH + cc;
        uint32_t so = (uint32_t)(r * SV + cc) * 2;
        cp16(base + 2 * AV_PT2 + so, vh + g);
        cp16(base + 2 * AV_PT2 + AV_VT2 + so, vl + g);
    }
    CP_COMMIT();
}

__global__ void __launch_bounds__(256) av_mma(
    const bf16* __restrict__ phA, const bf16* __restrict__ plA,
    const bf16* __restrict__ vhA, const bf16* __restrict__ vlA,
    bf16* __restrict__ ohi, bf16* __restrict__ olo) {
    int qt = blockIdx.x, bh = blockIdx.y;
    int b = bh >> 4, h = bh & 15;
    int tid = threadIdx.x;
    int wid = tid >> 5, lane = tid & 31;
    int wm = wid & 3, wn = wid >> 2;

    extern __shared__ char dyn[];
    uint32_t sb = smem_u32(dyn);

    const bf16* ph = phA + (size_t)bh * T * T;
    const bf16* pl = plA + (size_t)bh * T * T;
    const bf16* vh = vhA + (size_t)bh * T * DH;
    const bf16* vl = vlA + (size_t)bh * T * DH;

    float c[2][4][4];
#pragma unroll
    for (int i = 0; i < 2; i++)
#pragma unroll
        for (int j = 0; j < 4; j++)
#pragma unroll
            for (int q = 0; q < 4; q++) c[i][j][q] = 0.f;

    int a_row = wm * 32 + ((lane >> 3) & 1) * 8 + (lane & 7);
    int a_kc  = (lane >> 4) * 8;
    int v_k   = lane & 15;
    int v_n   = (lane >> 4) * 8;

    int nk = 2 * qt + 2;
    av_issue(sb, 0, 0, qt, tid, ph, pl, vh, vl);
    for (int kt = 0; kt < nk; kt++) {
        if (kt + 1 < nk) { av_issue(sb, (kt + 1) & 1, kt + 1, qt, tid, ph, pl, vh, vl); CP_WAIT1(); }
        else CP_WAIT0();
        __syncthreads();
        uint32_t uPh = sb + (kt & 1) * AV_STG2;
        uint32_t uPl = uPh + AV_PT2;
        uint32_t uVh = uPh + 2 * AV_PT2;
        uint32_t uVl = uVh + AV_VT2;
#pragma unroll
        for (int ks = 0; ks < 4; ks++) {
            uint32_t ah[2][4], al[2][4], bh2[2][4], bl2[2][4];
#pragma unroll
            for (int ma = 0; ma < 2; ma++) {
                uint32_t off = ((a_row + ma * 16) * SPK + a_kc + ks * 16) * 2;
                LDSM4(ah[ma][0], ah[ma][1], ah[ma][2], ah[ma][3], uPh + off);
                LDSM4(al[ma][0], al[ma][1], al[ma][2], al[ma][3], uPl + off);
            }
#pragma unroll
            for (int n16 = 0; n16 < 2; n16++) {
                uint32_t off = ((ks * 16 + v_k) * SV + wn * 32 + n16 * 16 + v_n) * 2;
                LDSM4T(bh2[n16][0], bh2[n16][1], bh2[n16][2], bh2[n16][3], uVh + off);
                LDSM4T(bl2[n16][0], bl2[n16][1], bl2[n16][2], bl2[n16][3], uVl + off);
            }
#pragma unroll
            for (int ma = 0; ma < 2; ma++)
#pragma unroll
                for (int nb = 0; nb < 4; nb++) {
                    int n2 = nb >> 1, o = (nb & 1) * 2;
                    MMA16816(c[ma][nb], ah[ma], bh2[n2][o], bh2[n2][o + 1]);
                    MMA16816(c[ma][nb], ah[ma], bl2[n2][o], bl2[n2][o + 1]);
                    MMA16816(c[ma][nb], al[ma], bh2[n2][o], bh2[n2][o + 1]);
                }
        }
        __syncthreads();
    }

    int t0 = qt * 128 + wm * 32 + (lane >> 2);
#pragma unroll
    for (int ma = 0; ma < 2; ma++) {
#pragma unroll
        for (int nb = 0; nb < 4; nb++) {
            int d = wn * 32 + nb * 8 + (lane & 3) * 2;
#pragma unroll
            for (int half = 0; half < 2; half++) {
                int t = t0 + ma * 16 + half * 8;
                size_t idx = ((size_t)(b * T + t)) * D_MODEL + h * DH + d;
                float y0 = c[ma][nb][half * 2 + 0];
                float y1 = c[ma][nb][half * 2 + 1];
                bf16 h0 = __float2bfloat16(y0);
                bf16 h1 = __float2bfloat16(y1);
                bf162 hv; hv.x = h0; hv.y = h1;
                bf162 lv;
                lv.x = __float2bfloat16(y0 - __bfloat162float(h0));
                lv.y = __float2bfloat16(y1 - __bfloat162float(h1));
                *(bf162*)&ohi[idx] = hv;
                *(bf162*)&olo[idx] = lv;
            }
        }
    }
}

// ---------------------------------------------------------------------------
extern "C" void kernel_launch(void* const* d_in, const int* in_sizes, int n_in,
                              void* d_out, int out_size) {
    (void)in_sizes; (void)n_in; (void)out_size;
    const float* x     = (const float*)d_in[0];
    const float* ln_g  = (const float*)d_in[1];
    const float* ln_b  = (const float*)d_in[2];
    const float* qkv_w = (const float*)d_in[3];
    const float* qkv_b = (const float*)d_in[4];
    const float* out_w = (const float*)d_in[5];
    const float* out_b = (const float*)d_in[6];

    float* xout = (float*)d_out;
    float* attn = xout + (size_t)BT * D_MODEL;

    static bf16 *p_hhi = nullptr, *p_hlo, *p_wqh, *p_wql, *p_woh, *p_wol;
    static bf16 *p_qh, *p_ql, *p_kh, *p_kl, *p_vh, *p_vl, *p_aoh, *p_aol;
    static bf16 *p_ph, *p_pl;
    if (!p_hhi) {
        cudaGetSymbolAddress((void**)&p_hhi, g_h_hi);
        cudaGetSymbolAddress((void**)&p_hlo, g_h_lo);
        cudaGetSymbolAddress((void**)&p_wqh, g_wq_hi);
        cudaGetSymbolAddress((void**)&p_wql, g_wq_lo);
        cudaGetSymbolAddress((void**)&p_woh, g_wo_hi);
        cudaGetSymbolAddress((void**)&p_wol, g_wo_lo);
        cudaGetSymbolAddress((void**)&p_qh, g_q_hi);
        cudaGetSymbolAddress((void**)&p_ql, g_q_lo);
        cudaGetSymbolAddress((void**)&p_kh, g_k_hi);
        cudaGetSymbolAddress((void**)&p_kl, g_k_lo);
        cudaGetSymbolAddress((void**)&p_vh, g_v_hi);
        cudaGetSymbolAddress((void**)&p_vl, g_v_lo);
        cudaGetSymbolAddress((void**)&p_aoh, g_ao_hi);
        cudaGetSymbolAddress((void**)&p_aol, g_ao_lo);
        cudaGetSymbolAddress((void**)&p_ph, g_p_hi);
        cudaGetSymbolAddress((void**)&p_pl, g_p_lo);
        cudaFuncSetAttribute(gemm_mma_qkv, cudaFuncAttributeMaxDynamicSharedMemorySize, GEMM_SMEM);
        cudaFuncSetAttribute(gemm_mma_out, cudaFuncAttributeMaxDynamicSharedMemorySize, GEMM_SMEM);
        cudaFuncSetAttribute(scores_mma, cudaFuncAttributeMaxDynamicSharedMemorySize, SCORES_SMEM);
        cudaFuncSetAttribute(av_mma, cudaFuncAttributeMaxDynamicSharedMemorySize, AV_SMEM);
    }

    ln_kernel<<<BT, 256>>>(x, ln_g, ln_b, p_hhi, p_hlo);
    tsplit_kernel<<<dim3(QKV_N / 32, D_MODEL / 32), dim3(32, 8)>>>(qkv_w, p_wqh, p_wql, D_MODEL, QKV_N);
    tsplit_kernel<<<dim3(D_MODEL / 32, D_MODEL / 32), dim3(32, 8)>>>(out_w, p_woh, p_wol, D_MODEL, D_MODEL);

    gemm_mma_qkv<<<dim3(QKV_N / 128, BT / 128), 256, GEMM_SMEM>>>(
        p_hhi, p_hlo, p_wqh, p_wql, qkv_b, p_qh, p_ql, p_kh, p_kl, p_vh, p_vl);

    scores_mma<<<dim3(16, 16, 32), 256, SCORES_SMEM>>>(p_qh, p_ql, p_kh, p_kl, attn);
    softmax_kernel<<<BATCH * NH * T, 256>>>(attn, p_ph, p_pl);
    av_mma<<<dim3(16, 32), 256, AV_SMEM>>>(p_ph, p_pl, p_vh, p_vl, p_aoh, p_aol);

    gemm_mma_out<<<dim3(D_MODEL / 128, BT / 128), 256, GEMM_SMEM>>>(
        p_aoh, p_aol, p_woh, p_wol, out_b, x, xout);
}

// round 9
// speedup vs baseline: 2.3775x; 1.0646x over previous
#include <cuda_runtime.h>
#include <cuda_bf16.h>
#include <cstdint>
#include <math.h>

#define D_MODEL 1024
#define NH      16
#define DH      64
#define BATCH   2
#define T       2048
#define BT      4096
#define QKV_N   3072

typedef __nv_bfloat16 bf16;
typedef __nv_bfloat162 bf162;

// ---------------------------------------------------------------------------
// Scratch
// ---------------------------------------------------------------------------
__device__ bf16 g_h_hi[(size_t)BT * D_MODEL];
__device__ bf16 g_h_lo[(size_t)BT * D_MODEL];
__device__ bf16 g_wq_hi[(size_t)QKV_N * D_MODEL];
__device__ bf16 g_wq_lo[(size_t)QKV_N * D_MODEL];
__device__ bf16 g_wo_hi[(size_t)D_MODEL * D_MODEL];
__device__ bf16 g_wo_lo[(size_t)D_MODEL * D_MODEL];
__device__ bf16 g_q_hi[(size_t)32 * T * DH];
__device__ bf16 g_q_lo[(size_t)32 * T * DH];
__device__ bf16 g_k_hi[(size_t)32 * T * DH];
__device__ bf16 g_k_lo[(size_t)32 * T * DH];
__device__ bf16 g_v_hi[(size_t)32 * T * DH];
__device__ bf16 g_v_lo[(size_t)32 * T * DH];
__device__ bf16 g_ao_hi[(size_t)BT * D_MODEL];
__device__ bf16 g_ao_lo[(size_t)BT * D_MODEL];
// softmax stats
__device__ float2 g_part[(size_t)32 * T * 16];   // per (row, ktile) partial (m, sumexp)
__device__ float  g_m[(size_t)32 * T];
__device__ float  g_inv[(size_t)32 * T];

// ---------------------------------------------------------------------------
// Helpers
// ---------------------------------------------------------------------------
__device__ __forceinline__ uint32_t smem_u32(const void* p) {
    uint32_t a;
    asm("{ .reg .u64 t; cvta.to.shared.u64 t, %1; cvt.u32.u64 %0, t; }" : "=r"(a) : "l"(p));
    return a;
}
__device__ __forceinline__ void cp16(uint32_t dst, const void* src) {
    asm volatile("cp.async.cg.shared.global [%0], [%1], 16;" :: "r"(dst), "l"(src));
}
#define CP_COMMIT() asm volatile("cp.async.commit_group;" ::: "memory")
#define CP_WAIT0()  asm volatile("cp.async.wait_group 0;" ::: "memory")
#define CP_WAIT1()  asm volatile("cp.async.wait_group 1;" ::: "memory")
#define LDSM4(r0, r1, r2, r3, addr)                                              \
    asm volatile("ldmatrix.sync.aligned.m8n8.x4.shared.b16 {%0,%1,%2,%3}, [%4];" \
                 : "=r"(r0), "=r"(r1), "=r"(r2), "=r"(r3) : "r"(addr))
#define LDSM4T(r0, r1, r2, r3, addr)                                                   \
    asm volatile("ldmatrix.sync.aligned.m8n8.x4.trans.shared.b16 {%0,%1,%2,%3}, [%4];" \
                 : "=r"(r0), "=r"(r1), "=r"(r2), "=r"(r3) : "r"(addr))
#define MMA16816(c, a, b0, b1)                                                   \
    asm volatile("mma.sync.aligned.m16n8k16.row.col.f32.bf16.bf16.f32 "          \
                 "{%0,%1,%2,%3}, {%4,%5,%6,%7}, {%8,%9}, {%0,%1,%2,%3};"         \
                 : "+f"((c)[0]), "+f"((c)[1]), "+f"((c)[2]), "+f"((c)[3])        \
                 : "r"((a)[0]), "r"((a)[1]), "r"((a)[2]), "r"((a)[3]),           \
                   "r"(b0), "r"(b1))

__device__ __forceinline__ void ms_merge(float& m, float& s, float om, float os) {
    float M = fmaxf(m, om);
    s = s * __expf(m - M) + os * __expf(om - M);
    m = M;
}

// ---------------------------------------------------------------------------
// LayerNorm -> bf16 hi/lo split
// ---------------------------------------------------------------------------
__global__ void ln_kernel(const float* __restrict__ x, const float* __restrict__ gam,
                          const float* __restrict__ bet,
                          bf16* __restrict__ ohi, bf16* __restrict__ olo) {
    int row = blockIdx.x;
    const float* xr = x + (size_t)row * D_MODEL;
    float v[4];
    float s = 0.f, s2 = 0.f;
#pragma unroll
    for (int i = 0; i < 4; i++) {
        v[i] = xr[threadIdx.x + i * 256];
        s += v[i]; s2 += v[i] * v[i];
    }
#pragma unroll
    for (int o = 16; o > 0; o >>= 1) {
        s  += __shfl_xor_sync(~0u, s, o);
        s2 += __shfl_xor_sync(~0u, s2, o);
    }
    __shared__ float rs[8], rs2[8];
    int wid = threadIdx.x >> 5, lid = threadIdx.x & 31;
    if (lid == 0) { rs[wid] = s; rs2[wid] = s2; }
    __syncthreads();
    s = 0.f; s2 = 0.f;
#pragma unroll
    for (int i = 0; i < 8; i++) { s += rs[i]; s2 += rs2[i]; }
    float mu  = s * (1.f / D_MODEL);
    float var = s2 * (1.f / D_MODEL) - mu * mu;
    float inv = rsqrtf(var + 1e-5f);
#pragma unroll
    for (int i = 0; i < 4; i++) {
        int c = threadIdx.x + i * 256;
        float y = (v[i] - mu) * inv * gam[c] + bet[c];
        bf16 h = __float2bfloat16(y);
        ohi[(size_t)row * D_MODEL + c] = h;
        olo[(size_t)row * D_MODEL + c] = __float2bfloat16(y - __bfloat162float(h));
    }
}

// ---------------------------------------------------------------------------
// Transpose + bf16 split: W[K][N] -> out[N][K]
// ---------------------------------------------------------------------------
__global__ void tsplit_kernel(const float* __restrict__ W,
                              bf16* __restrict__ hi, bf16* __restrict__ lo,
                              int K, int N) {
    __shared__ float t[32][33];
    int n0 = blockIdx.x * 32, k0 = blockIdx.y * 32;
    int tx = threadIdx.x, ty = threadIdx.y;
#pragma unroll
    for (int j = 0; j < 4; j++)
        t[ty + j * 8][tx] = W[(size_t)(k0 + ty + j * 8) * N + n0 + tx];
    __syncthreads();
#pragma unroll
    for (int j = 0; j < 4; j++) {
        float v = t[tx][ty + j * 8];
        size_t o = (size_t)(n0 + ty + j * 8) * K + k0 + tx;
        bf16 h = __float2bfloat16(v);
        hi[o] = h;
        lo[o] = __float2bfloat16(v - __bfloat162float(h));
    }
}

// ---------------------------------------------------------------------------
// Pipelined HMMA GEMMs: 512 threads, block 128x128x32, warp tile 32x32 (4x4)
// ---------------------------------------------------------------------------
#define SA 40
#define GT_TILE2  (128 * SA * 2)
#define GT_STG2   (4 * GT_TILE2)
#define GEMM_SMEM (2 * GT_STG2)

__device__ __forceinline__ void gemm_issue(
    uint32_t sb, int st, int kc, int bm, int bn, int tid, int K,
    const bf16* __restrict__ Ah, const bf16* __restrict__ Al,
    const bf16* __restrict__ Bh, const bf16* __restrict__ Bl) {
    int r = tid >> 2, cc = (tid & 3) * 8;   // 512 threads: one cp16 per tile
    int c0 = kc * 32;
    uint32_t base = sb + (uint32_t)st * GT_STG2;
    size_t ga = (size_t)(bm * 128 + r) * K + c0 + cc;
    size_t gb = (size_t)(bn * 128 + r) * K + c0 + cc;
    uint32_t so = (uint32_t)(r * SA + cc) * 2;
    cp16(base + so, Ah + ga);
    cp16(base + GT_TILE2 + so, Al + ga);
    cp16(base + 2 * GT_TILE2 + so, Bh + gb);
    cp16(base + 3 * GT_TILE2 + so, Bl + gb);
    CP_COMMIT();
}

#define GEMM_MAINLOOP(K_)                                                        \
    int a_row = wm * 32 + ((lane >> 3) & 1) * 8 + (lane & 7);                    \
    int a_kc  = (lane >> 4) * 8;                                                 \
    int b_row = wn * 32 + (lane >> 4) * 8 + (lane & 7);                          \
    int b_kc  = ((lane >> 3) & 1) * 8;                                           \
    float c[2][4][4];                                                            \
    _Pragma("unroll") for (int i = 0; i < 2; i++)                                \
    _Pragma("unroll") for (int j = 0; j < 4; j++)                                \
    _Pragma("unroll") for (int q = 0; q < 4; q++) c[i][j][q] = 0.f;              \
    const int NK = (K_) / 32;                                                    \
    gemm_issue(sb, 0, 0, bm, bn, tid, (K_), Ah, Al, Bh, Bl);                     \
    for (int kc = 0; kc < NK; kc++) {                                            \
        if (kc + 1 < NK) { gemm_issue(sb, (kc + 1) & 1, kc + 1, bm, bn, tid,     \
                                      (K_), Ah, Al, Bh, Bl); CP_WAIT1(); }       \
        else CP_WAIT0();                                                         \
        __syncthreads();                                                         \
        uint32_t uAh = sb + (kc & 1) * GT_STG2;                                  \
        uint32_t uAl = uAh + GT_TILE2;                                           \
        uint32_t uBh = uAh + 2 * GT_TILE2;                                       \
        uint32_t uBl = uAh + 3 * GT_TILE2;                                       \
        _Pragma("unroll")                                                        \
        for (int ks = 0; ks < 2; ks++) {                                         \
            uint32_t ah[2][4], al[2][4], bh[2][4], bl[2][4];                     \
            _Pragma("unroll")                                                    \
            for (int ma = 0; ma < 2; ma++) {                                     \
                uint32_t off = ((a_row + ma * 16) * SA + a_kc + ks * 16) * 2;    \
                LDSM4(ah[ma][0], ah[ma][1], ah[ma][2], ah[ma][3], uAh + off);    \
                LDSM4(al[ma][0], al[ma][1], al[ma][2], al[ma][3], uAl + off);    \
            }                                                                    \
            _Pragma("unroll")                                                    \
            for (int nb2 = 0; nb2 < 2; nb2++) {                                  \
                uint32_t off = ((b_row + nb2 * 16) * SA + b_kc + ks * 16) * 2;   \
                LDSM4(bh[nb2][0], bh[nb2][1], bh[nb2][2], bh[nb2][3], uBh + off);\
                LDSM4(bl[nb2][0], bl[nb2][1], bl[nb2][2], bl[nb2][3], uBl + off);\
            }                                                                    \
            _Pragma("unroll")                                                    \
            for (int ma = 0; ma < 2; ma++)                                       \
            _Pragma("unroll")                                                    \
            for (int nb = 0; nb < 4; nb++) {                                     \
                int n2 = nb >> 1, o = (nb & 1) * 2;                              \
                MMA16816(c[ma][nb], ah[ma], bh[n2][o], bh[n2][o + 1]);           \
                MMA16816(c[ma][nb], ah[ma], bl[n2][o], bl[n2][o + 1]);           \
                MMA16816(c[ma][nb], al[ma], bh[n2][o], bh[n2][o + 1]);           \
            }                                                                    \
        }                                                                        \
        __syncthreads();                                                         \
    }

__global__ void __launch_bounds__(512) gemm_mma_qkv(
    const bf16* __restrict__ Ah, const bf16* __restrict__ Al,
    const bf16* __restrict__ Bh, const bf16* __restrict__ Bl,
    const float* __restrict__ bias,
    bf16* __restrict__ qhi, bf16* __restrict__ qlo,
    bf16* __restrict__ khi, bf16* __restrict__ klo,
    bf16* __restrict__ vhi, bf16* __restrict__ vlo) {
    extern __shared__ char dyn[];
    uint32_t sb = smem_u32(dyn);
    int tid = threadIdx.x;
    int wid = tid >> 5, lane = tid & 31;
    int wm = wid & 3, wn = wid >> 2;
    int bm = blockIdx.y, bn = blockIdx.x;

    GEMM_MAINLOOP(D_MODEL)

    int r0 = bm * 128 + wm * 32 + (lane >> 2);
#pragma unroll
    for (int ma = 0; ma < 2; ma++) {
#pragma unroll
        for (int nb = 0; nb < 4; nb++) {
            int col = bn * 128 + wn * 32 + nb * 8 + (lane & 3) * 2;
            int hg = col >> 6;
            int sec = hg >> 4;
            int h = hg & 15;
            int c64 = col & 63;
            bf16* dh = (sec == 0) ? qhi : (sec == 1) ? khi : vhi;
            bf16* dl = (sec == 0) ? qlo : (sec == 1) ? klo : vlo;
            float bx = bias[col], by = bias[col + 1];
#pragma unroll
            for (int half = 0; half < 2; half++) {
                int row = r0 + ma * 16 + half * 8;
                int t = row & (T - 1), b = row >> 11;
                size_t idx = (((size_t)(b * NH + h)) * T + t) * DH + c64;
                float y0 = c[ma][nb][half * 2 + 0] + bx;
                float y1 = c[ma][nb][half * 2 + 1] + by;
                bf16 h0 = __float2bfloat16(y0);
                bf16 h1 = __float2bfloat16(y1);
                bf162 hv; hv.x = h0; hv.y = h1;
                bf162 lv;
                lv.x = __float2bfloat16(y0 - __bfloat162float(h0));
                lv.y = __float2bfloat16(y1 - __bfloat162float(h1));
                *(bf162*)&dh[idx] = hv;
                *(bf162*)&dl[idx] = lv;
            }
        }
    }
}

__global__ void __launch_bounds__(512) gemm_mma_out(
    const bf16* __restrict__ Ah, const bf16* __restrict__ Al,
    const bf16* __restrict__ Bh, const bf16* __restrict__ Bl,
    const float* __restrict__ bias, const float* __restrict__ res,
    float* __restrict__ C) {
    const int N = D_MODEL;
    extern __shared__ char dyn[];
    uint32_t sb = smem_u32(dyn);
    int tid = threadIdx.x;
    int wid = tid >> 5, lane = tid & 31;
    int wm = wid & 3, wn = wid >> 2;
    int bm = blockIdx.y, bn = blockIdx.x;

    GEMM_MAINLOOP(D_MODEL)

    int r0 = bm * 128 + wm * 32 + (lane >> 2);
#pragma unroll
    for (int ma = 0; ma < 2; ma++) {
#pragma unroll
        for (int nb = 0; nb < 4; nb++) {
            int col = bn * 128 + wn * 32 + nb * 8 + (lane & 3) * 2;
            int ra = r0 + ma * 16, rb = ra + 8;
            float2 o0, o1;
            o0.x = c[ma][nb][0] + bias[col];
            o0.y = c[ma][nb][1] + bias[col + 1];
            o1.x = c[ma][nb][2] + bias[col];
            o1.y = c[ma][nb][3] + bias[col + 1];
            float2 r2a = *(const float2*)&res[(size_t)ra * N + col];
            float2 r2b = *(const float2*)&res[(size_t)rb * N + col];
            o0.x += r2a.x; o0.y += r2a.y;
            o1.x += r2b.x; o1.y += r2b.y;
            *(float2*)&C[(size_t)ra * N + col] = o0;
            *(float2*)&C[(size_t)rb * N + col] = o1;
        }
    }
}

// ---------------------------------------------------------------------------
// Scores via HMMA + per-block softmax stats.
// Writes raw S (masked = -1e30); upper tiles zero-filled.
// Stats partial (m, sumexp) per (row, ktile) -> g_part.
// ---------------------------------------------------------------------------
#define SK 72
#define SCORES_SMEM (4 * 128 * SK * 2)

__global__ void __launch_bounds__(256) scores_mma(
    const bf16* __restrict__ qh, const bf16* __restrict__ ql,
    const bf16* __restrict__ kh, const bf16* __restrict__ kl,
    float* __restrict__ attn, float2* __restrict__ part) {
    int kt = blockIdx.x, qt = blockIdx.y, bh = blockIdx.z;
    int tid = threadIdx.x;
    float* ablk = attn + ((size_t)bh * T + qt * 128) * T + kt * 128;

    if (kt > qt) {
        int r = tid >> 1, c0 = (tid & 1) * 64;
        float4 z = make_float4(0.f, 0.f, 0.f, 0.f);
#pragma unroll
        for (int j = 0; j < 16; j++)
            *(float4*)&ablk[(size_t)r * T + c0 + j * 4] = z;
        return;
    }

    extern __shared__ char dyn[];
    bf16* sQh = (bf16*)dyn;
    bf16* sQl = sQh + 128 * SK;
    bf16* sKh = sQl + 128 * SK;
    bf16* sKl = sKh + 128 * SK;
    __shared__ float2 sstat[128][2];

    const bf16* qhb = qh + ((size_t)bh * T + qt * 128) * DH;
    const bf16* qlb = ql + ((size_t)bh * T + qt * 128) * DH;
    const bf16* khb = kh + ((size_t)bh * T + kt * 128) * DH;
    const bf16* klb = kl + ((size_t)bh * T + kt * 128) * DH;

#pragma unroll
    for (int it = 0; it < 4; it++) {
        int idx = tid + it * 256;
        int r = idx >> 3, cc = (idx & 7) * 8;
        int so = r * SK + cc;
        size_t go = (size_t)r * DH + cc;
        *(uint4*)&sQh[so] = *(const uint4*)&qhb[go];
        *(uint4*)&sQl[so] = *(const uint4*)&qlb[go];
        *(uint4*)&sKh[so] = *(const uint4*)&khb[go];
        *(uint4*)&sKl[so] = *(const uint4*)&klb[go];
    }
    __syncthreads();

    int wid = tid >> 5, lane = tid & 31;
    int wm = wid & 3, wn = wid >> 2;
    uint32_t uQh = smem_u32(sQh), uQl = smem_u32(sQl);
    uint32_t uKh = smem_u32(sKh), uKl = smem_u32(sKl);

    int a_row = wm * 32 + ((lane >> 3) & 1) * 8 + (lane & 7);
    int a_kc  = (lane >> 4) * 8;
    int b_row = wn * 64 + (lane >> 4) * 8 + (lane & 7);
    int b_kc  = ((lane >> 3) & 1) * 8;

    float c[2][8][4];
#pragma unroll
    for (int i = 0; i < 2; i++)
#pragma unroll
        for (int j = 0; j < 8; j++)
#pragma unroll
            for (int q = 0; q < 4; q++) c[i][j][q] = 0.f;

#pragma unroll
    for (int ks = 0; ks < 4; ks++) {
        uint32_t ah[2][4], al[2][4], bh2[4][4], bl2[4][4];
#pragma unroll
        for (int ma = 0; ma < 2; ma++) {
            uint32_t off = ((a_row + ma * 16) * SK + a_kc + ks * 16) * 2;
            LDSM4(ah[ma][0], ah[ma][1], ah[ma][2], ah[ma][3], uQh + off);
            LDSM4(al[ma][0], al[ma][1], al[ma][2], al[ma][3], uQl + off);
        }
#pragma unroll
        for (int nb2 = 0; nb2 < 4; nb2++) {
            uint32_t off = ((b_row + nb2 * 16) * SK + b_kc + ks * 16) * 2;
            LDSM4(bh2[nb2][0], bh2[nb2][1], bh2[nb2][2], bh2[nb2][3], uKh + off);
            LDSM4(bl2[nb2][0], bl2[nb2][1], bl2[nb2][2], bl2[nb2][3], uKl + off);
        }
#pragma unroll
        for (int ma = 0; ma < 2; ma++)
#pragma unroll
            for (int nb = 0; nb < 8; nb++) {
                int n2 = nb >> 1, o = (nb & 1) * 2;
                MMA16816(c[ma][nb], ah[ma], bh2[n2][o], bh2[n2][o + 1]);
                MMA16816(c[ma][nb], ah[ma], bl2[n2][o], bl2[n2][o + 1]);
                MMA16816(c[ma][nb], al[ma], bh2[n2][o], bh2[n2][o + 1]);
            }
    }

    bool diag = (qt == kt);
    // Write raw S (masked = -1e30) and compute per-row stats
#pragma unroll
    for (int ma = 0; ma < 2; ma++) {
#pragma unroll
        for (int half = 0; half < 2; half++) {
            int lrow = wm * 32 + ma * 16 + half * 8 + (lane >> 2);
            // masked values in registers
            float vv[8][2];
#pragma unroll
            for (int nb = 0; nb < 8; nb++) {
                int colc = wn * 64 + nb * 8 + (lane & 3) * 2;
                float v0 = c[ma][nb][half * 2 + 0] * 0.125f;
                float v1 = c[ma][nb][half * 2 + 1] * 0.125f;
                if (diag) {
                    if (colc > lrow) v0 = -1e30f;
                    if (colc + 1 > lrow) v1 = -1e30f;
                }
                vv[nb][0] = v0; vv[nb][1] = v1;
                float2 o2; o2.x = v0; o2.y = v1;
                *(float2*)&ablk[(size_t)lrow * T + colc] = o2;
            }
            float mt = -1e30f;
#pragma unroll
            for (int nb = 0; nb < 8; nb++) {
                mt = fmaxf(mt, vv[nb][0]);
                mt = fmaxf(mt, vv[nb][1]);
            }
            float st = 0.f;
#pragma unroll
            for (int nb = 0; nb < 8; nb++) {
                st += __expf(vv[nb][0] - mt);
                st += __expf(vv[nb][1] - mt);
            }
            // merge across the 4 lanes sharing this row
#pragma unroll
            for (int o = 1; o < 4; o <<= 1) {
                float om = __shfl_xor_sync(~0u, mt, o);
                float os = __shfl_xor_sync(~0u, st, o);
                ms_merge(mt, st, om, os);
            }
            if ((lane & 3) == 0) sstat[lrow][wn] = make_float2(mt, st);
        }
    }
    __syncthreads();
    if (tid < 128) {
        float2 p0 = sstat[tid][0], p1 = sstat[tid][1];
        float m = p0.x, s = p0.y;
        ms_merge(m, s, p1.x, p1.y);
        part[((size_t)bh * T + qt * 128 + tid) * 16 + kt] = make_float2(m, s);
    }
}

// ---------------------------------------------------------------------------
// Reduce per-row partials -> (m, 1/sum)
// ---------------------------------------------------------------------------
__global__ void reduce_stats(const float2* __restrict__ part,
                             float* __restrict__ mA, float* __restrict__ invA) {
    int row = blockIdx.x * 256 + threadIdx.x;   // 0 .. 32*T-1
    int r = row & (T - 1);
    int nkb = (r >> 7) + 1;
    float m = -1e30f, s = 0.f;
    const float2* p = part + (size_t)row * 16;
    for (int i = 0; i < nkb; i++) {
        float2 v = p[i];
        ms_merge(m, s, v.x, v.y);
    }
    mA[row] = m;
    invA[row] = 1.f / s;
}

// ---------------------------------------------------------------------------
// av: reads raw S fp32 (pipelined), normalizes (exp(s-m)*inv), writes attn
// in place, splits P->bf16 hi/lo in smem, MMA with V -> O (bf16 hi/lo).
// ---------------------------------------------------------------------------
#define AVS_MS    0
#define AVS_INV   512
#define AVS_S     1024
#define AVS_SSTG  (128 * 68 * 4)                 // 34816
#define AVS_V     (1024 + 2 * AVS_SSTG)          // 70656
#define AVS_VSTG  (2 * 64 * 72 * 2)              // 18432 (Vh + Vl)
#define AVS_PH    (AVS_V + 2 * AVS_VSTG)         // 107520
#define AVS_PL    (AVS_PH + 128 * 72 * 2)        // 125952
#define AV_SMEM   (AVS_PL + 128 * 72 * 2)        // 144384
#define SPK 72
#define SV  72

__device__ __forceinline__ void av_issue(
    uint32_t sb, int st, int kt, int tid,
    const float* __restrict__ sblk,   // attn + (bh*T + qt*128)*T
    const bf16* __restrict__ vh, const bf16* __restrict__ vl) {
    uint32_t base = sb + AVS_S + (uint32_t)st * AVS_SSTG;
#pragma unroll
    for (int p = 0; p < 8; p++) {
        int idx = tid + p * 256;
        int r = idx >> 4, c4 = (idx & 15) * 4;
        cp16(base + (uint32_t)(r * 68 + c4) * 4, sblk + (size_t)r * T + kt * 64 + c4);
    }
    uint32_t vb = sb + AVS_V + (uint32_t)st * AVS_VSTG;
#pragma unroll
    for (int p = 0; p < 2; p++) {
        int idx = tid + p * 256;
        int r = idx >> 3, cc = (idx & 7) * 8;
        size_t g = (size_t)(kt * 64 + r) * DH + cc;
        uint32_t so = (uint32_t)(r * SV + cc) * 2;
        cp16(vb + so, vh + g);
        cp16(vb + 64 * SV * 2 + so, vl + g);
    }
    CP_COMMIT();
}

__global__ void __launch_bounds__(256) av_mma(
    float* __restrict__ attn,
    const float* __restrict__ mA, const float* __restrict__ invA,
    const bf16* __restrict__ vhA, const bf16* __restrict__ vlA,
    bf16* __restrict__ ohi, bf16* __restrict__ olo) {
    int qt = blockIdx.x, bh = blockIdx.y;
    int b = bh >> 4, h = bh & 15;
    int tid = threadIdx.x;
    int wid = tid >> 5, lane = tid & 31;
    int wm = wid & 3, wn = wid >> 2;

    extern __shared__ char dyn[];
    uint32_t sb = smem_u32(dyn);
    float* ms  = (float*)(dyn + AVS_MS);
    float* ivs = (float*)(dyn + AVS_INV);

    float* sblk = attn + ((size_t)bh * T + qt * 128) * T;
    const bf16* vh = vhA + (size_t)bh * T * DH;
    const bf16* vl = vlA + (size_t)bh * T * DH;

    if (tid < 128) {
        int row = bh * T + qt * 128 + tid;
        ms[tid] = mA[row];
        ivs[tid] = invA[row];
    }

    float c[2][4][4];
#pragma unroll
    for (int i = 0; i < 2; i++)
#pragma unroll
        for (int j = 0; j < 4; j++)
#pragma unroll
            for (int q = 0; q < 4; q++) c[i][j][q] = 0.f;

    int a_row = wm * 32 + ((lane >> 3) & 1) * 8 + (lane & 7);
    int a_kc  = (lane >> 4) * 8;
    int v_k   = lane & 15;
    int v_n   = (lane >> 4) * 8;
    uint32_t uPh = sb + AVS_PH, uPl = sb + AVS_PL;

    int nk = 2 * qt + 2;
    av_issue(sb, 0, 0, tid, sblk, vh, vl);
    for (int kt = 0; kt < nk; kt++) {
        if (kt + 1 < nk) { av_issue(sb, (kt + 1) & 1, kt + 1, tid, sblk, vh, vl); CP_WAIT1(); }
        else CP_WAIT0();
        __syncthreads();
        // Convert: p = exp(s - m) * inv ; write attn ; split to bf16
        {
            uint32_t sbase = sb + AVS_S + (uint32_t)(kt & 1) * AVS_SSTG;
            float* Sst = (float*)(dyn + AVS_S + (size_t)(kt & 1) * AVS_SSTG);
            bf16* Ph = (bf16*)(dyn + AVS_PH);
            bf16* Pl = (bf16*)(dyn + AVS_PL);
            (void)sbase;
#pragma unroll
            for (int p = 0; p < 8; p++) {
                int idx = tid + p * 256;
                int r = idx >> 4, c4 = (idx & 15) * 4;
                float4 s4 = *(float4*)&Sst[r * 68 + c4];
                float m = ms[r], iv = ivs[r];
                float p0 = __expf(s4.x - m) * iv;
                float p1 = __expf(s4.y - m) * iv;
                float p2 = __expf(s4.z - m) * iv;
                float p3 = __expf(s4.w - m) * iv;
                float4 o4; o4.x = p0; o4.y = p1; o4.z = p2; o4.w = p3;
                *(float4*)&sblk[(size_t)r * T + kt * 64 + c4] = o4;
                bf162 h0, h1, l0, l1;
                h0.x = __float2bfloat16(p0); h0.y = __float2bfloat16(p1);
                h1.x = __float2bfloat16(p2); h1.y = __float2bfloat16(p3);
                l0.x = __float2bfloat16(p0 - __bfloat162float(h0.x));
                l0.y = __float2bfloat16(p1 - __bfloat162float(h0.y));
                l1.x = __float2bfloat16(p2 - __bfloat162float(h1.x));
                l1.y = __float2bfloat16(p3 - __bfloat162float(h1.y));
                *(bf162*)&Ph[r * SPK + c4]     = h0;
                *(bf162*)&Ph[r * SPK + c4 + 2] = h1;
                *(bf162*)&Pl[r * SPK + c4]     = l0;
                *(bf162*)&Pl[r * SPK + c4 + 2] = l1;
            }
        }
        __syncthreads();
        uint32_t uVh = sb + AVS_V + (uint32_t)(kt & 1) * AVS_VSTG;
        uint32_t uVl = uVh + 64 * SV * 2;
#pragma unroll
        for (int ks = 0; ks < 4; ks++) {
            uint32_t ah[2][4], al[2][4], bh2[2][4], bl2[2][4];
#pragma unroll
            for (int ma = 0; ma < 2; ma++) {
                uint32_t off = ((a_row + ma * 16) * SPK + a_kc + ks * 16) * 2;
                LDSM4(ah[ma][0], ah[ma][1], ah[ma][2], ah[ma][3], uPh + off);
                LDSM4(al[ma][0], al[ma][1], al[ma][2], al[ma][3], uPl + off);
            }
#pragma unroll
            for (int n16 = 0; n16 < 2; n16++) {
                uint32_t off = ((ks * 16 + v_k) * SV + wn * 32 + n16 * 16 + v_n) * 2;
                LDSM4T(bh2[n16][0], bh2[n16][1], bh2[n16][2], bh2[n16][3], uVh + off);
                LDSM4T(bl2[n16][0], bl2[n16][1], bl2[n16][2], bl2[n16][3], uVl + off);
            }
#pragma unroll
            for (int ma = 0; ma < 2; ma++)
#pragma unroll
                for (int nb = 0; nb < 4; nb++) {
                    int n2 = nb >> 1, o = (nb & 1) * 2;
                    MMA16816(c[ma][nb], ah[ma], bh2[n2][o], bh2[n2][o + 1]);
                    MMA16816(c[ma][nb], ah[ma], bl2[n2][o], bl2[n2][o + 1]);
                    MMA16816(c[ma][nb], al[ma], bh2[n2][o], bh2[n2][o + 1]);
                }
        }
        __syncthreads();
    }

    int t0 = qt * 128 + wm * 32 + (lane >> 2);
#pragma unroll
    for (int ma = 0; ma < 2; ma++) {
#pragma unroll
        for (int nb = 0; nb < 4; nb++) {
            int d = wn * 32 + nb * 8 + (lane & 3) * 2;
#pragma unroll
            for (int half = 0; half < 2; half++) {
                int t = t0 + ma * 16 + half * 8;
                size_t idx = ((size_t)(b * T + t)) * D_MODEL + h * DH + d;
                float y0 = c[ma][nb][half * 2 + 0];
                float y1 = c[ma][nb][half * 2 + 1];
                bf16 h0 = __float2bfloat16(y0);
                bf16 h1 = __float2bfloat16(y1);
                bf162 hv; hv.x = h0; hv.y = h1;
                bf162 lv;
                lv.x = __float2bfloat16(y0 - __bfloat162float(h0));
                lv.y = __float2bfloat16(y1 - __bfloat162float(h1));
                *(bf162*)&ohi[idx] = hv;
                *(bf162*)&olo[idx] = lv;
            }
        }
    }
}

// ---------------------------------------------------------------------------
extern "C" void kernel_launch(void* const* d_in, const int* in_sizes, int n_in,
                              void* d_out, int out_size) {
    (void)in_sizes; (void)n_in; (void)out_size;
    const float* x     = (const float*)d_in[0];
    const float* ln_g  = (const float*)d_in[1];
    const float* ln_b  = (const float*)d_in[2];
    const float* qkv_w = (const float*)d_in[3];
    const float* qkv_b = (const float*)d_in[4];
    const float* out_w = (const float*)d_in[5];
    const float* out_b = (const float*)d_in[6];

    float* xout = (float*)d_out;
    float* attn = xout + (size_t)BT * D_MODEL;

    static bf16 *p_hhi = nullptr, *p_hlo, *p_wqh, *p_wql, *p_woh, *p_wol;
    static bf16 *p_qh, *p_ql, *p_kh, *p_kl, *p_vh, *p_vl, *p_aoh, *p_aol;
    static float2* p_part;
    static float *p_m, *p_inv;
    if (!p_hhi) {
        cudaGetSymbolAddress((void**)&p_hhi, g_h_hi);
        cudaGetSymbolAddress((void**)&p_hlo, g_h_lo);
        cudaGetSymbolAddress((void**)&p_wqh, g_wq_hi);
        cudaGetSymbolAddress((void**)&p_wql, g_wq_lo);
        cudaGetSymbolAddress((void**)&p_woh, g_wo_hi);
        cudaGetSymbolAddress((void**)&p_wol, g_wo_lo);
        cudaGetSymbolAddress((void**)&p_qh, g_q_hi);
        cudaGetSymbolAddress((void**)&p_ql, g_q_lo);
        cudaGetSymbolAddress((void**)&p_kh, g_k_hi);
        cudaGetSymbolAddress((void**)&p_kl, g_k_lo);
        cudaGetSymbolAddress((void**)&p_vh, g_v_hi);
        cudaGetSymbolAddress((void**)&p_vl, g_v_lo);
        cudaGetSymbolAddress((void**)&p_aoh, g_ao_hi);
        cudaGetSymbolAddress((void**)&p_aol, g_ao_lo);
        cudaGetSymbolAddress((void**)&p_part, g_part);
        cudaGetSymbolAddress((void**)&p_m, g_m);
        cudaGetSymbolAddress((void**)&p_inv, g_inv);
        cudaFuncSetAttribute(gemm_mma_qkv, cudaFuncAttributeMaxDynamicSharedMemorySize, GEMM_SMEM);
        cudaFuncSetAttribute(gemm_mma_out, cudaFuncAttributeMaxDynamicSharedMemorySize, GEMM_SMEM);
        cudaFuncSetAttribute(scores_mma, cudaFuncAttributeMaxDynamicSharedMemorySize, SCORES_SMEM);
        cudaFuncSetAttribute(av_mma, cudaFuncAttributeMaxDynamicSharedMemorySize, AV_SMEM);
    }

    ln_kernel<<<BT, 256>>>(x, ln_g, ln_b, p_hhi, p_hlo);
    tsplit_kernel<<<dim3(QKV_N / 32, D_MODEL / 32), dim3(32, 8)>>>(qkv_w, p_wqh, p_wql, D_MODEL, QKV_N);
    tsplit_kernel<<<dim3(D_MODEL / 32, D_MODEL / 32), dim3(32, 8)>>>(out_w, p_woh, p_wol, D_MODEL, D_MODEL);

    gemm_mma_qkv<<<dim3(QKV_N / 128, BT / 128), 512, GEMM_SMEM>>>(
        p_hhi, p_hlo, p_wqh, p_wql, qkv_b, p_qh, p_ql, p_kh, p_kl, p_vh, p_vl);

    scores_mma<<<dim3(16, 16, 32), 256, SCORES_SMEM>>>(p_qh, p_ql, p_kh, p_kl, attn, p_part);
    reduce_stats<<<(32 * T) / 256, 256>>>(p_part, p_m, p_inv);
    av_mma<<<dim3(16, 32), 256, AV_SMEM>>>(attn, p_m, p_inv, p_vh, p_vl, p_aoh, p_aol);

    gemm_mma_out<<<dim3(D_MODEL / 128, BT / 128), 512, GEMM_SMEM>>>(
        p_aoh, p_aol, p_woh, p_wol, out_b, x, xout);
}

// round 10
// speedup vs baseline: 2.4767x; 1.0417x over previous
#include <cuda_runtime.h>
#include <cuda_bf16.h>
#include <cstdint>
#include <math.h>

#define D_MODEL 1024
#define NH      16
#define DH      64
#define BATCH   2
#define T       2048
#define BT      4096
#define QKV_N   3072

typedef __nv_bfloat16 bf16;
typedef __nv_bfloat162 bf162;

// ---------------------------------------------------------------------------
// Scratch
// ---------------------------------------------------------------------------
__device__ bf16 g_h_hi[(size_t)BT * D_MODEL];
__device__ bf16 g_h_lo[(size_t)BT * D_MODEL];
__device__ bf16 g_wq_hi[(size_t)QKV_N * D_MODEL];
__device__ bf16 g_wq_lo[(size_t)QKV_N * D_MODEL];
__device__ bf16 g_wo_hi[(size_t)D_MODEL * D_MODEL];
__device__ bf16 g_wo_lo[(size_t)D_MODEL * D_MODEL];
__device__ bf16 g_q_hi[(size_t)32 * T * DH];
__device__ bf16 g_q_lo[(size_t)32 * T * DH];
__device__ bf16 g_k_hi[(size_t)32 * T * DH];
__device__ bf16 g_k_lo[(size_t)32 * T * DH];
__device__ bf16 g_v_hi[(size_t)32 * T * DH];
__device__ bf16 g_v_lo[(size_t)32 * T * DH];
__device__ bf16 g_ao_hi[(size_t)BT * D_MODEL];
__device__ bf16 g_ao_lo[(size_t)BT * D_MODEL];
__device__ float2 g_part[(size_t)32 * T * 16];
__device__ float  g_m[(size_t)32 * T];
__device__ float  g_inv[(size_t)32 * T];

// ---------------------------------------------------------------------------
// Helpers
// ---------------------------------------------------------------------------
__device__ __forceinline__ uint32_t smem_u32(const void* p) {
    uint32_t a;
    asm("{ .reg .u64 t; cvta.to.shared.u64 t, %1; cvt.u32.u64 %0, t; }" : "=r"(a) : "l"(p));
    return a;
}
__device__ __forceinline__ void cp16(uint32_t dst, const void* src) {
    asm volatile("cp.async.cg.shared.global [%0], [%1], 16;" :: "r"(dst), "l"(src));
}
#define CP_COMMIT() asm volatile("cp.async.commit_group;" ::: "memory")
#define CP_WAIT0()  asm volatile("cp.async.wait_group 0;" ::: "memory")
#define CP_WAIT1()  asm volatile("cp.async.wait_group 1;" ::: "memory")
#define LDSM4(r0, r1, r2, r3, addr)                                              \
    asm volatile("ldmatrix.sync.aligned.m8n8.x4.shared.b16 {%0,%1,%2,%3}, [%4];" \
                 : "=r"(r0), "=r"(r1), "=r"(r2), "=r"(r3) : "r"(addr))
#define LDSM4T(r0, r1, r2, r3, addr)                                                   \
    asm volatile("ldmatrix.sync.aligned.m8n8.x4.trans.shared.b16 {%0,%1,%2,%3}, [%4];" \
                 : "=r"(r0), "=r"(r1), "=r"(r2), "=r"(r3) : "r"(addr))
#define MMA16816(c, a, b0, b1)                                                   \
    asm volatile("mma.sync.aligned.m16n8k16.row.col.f32.bf16.bf16.f32 "          \
                 "{%0,%1,%2,%3}, {%4,%5,%6,%7}, {%8,%9}, {%0,%1,%2,%3};"         \
                 : "+f"((c)[0]), "+f"((c)[1]), "+f"((c)[2]), "+f"((c)[3])        \
                 : "r"((a)[0]), "r"((a)[1]), "r"((a)[2]), "r"((a)[3]),           \
                   "r"(b0), "r"(b1))

__device__ __forceinline__ void ms_merge(float& m, float& s, float om, float os) {
    float M = fmaxf(m, om);
    s = s * __expf(m - M) + os * __expf(om - M);
    m = M;
}
__device__ __forceinline__ uint32_t packbf(float a, float b) {
    bf162 v; v.x = __float2bfloat16(a); v.y = __float2bfloat16(b);
    return *(uint32_t*)&v;
}

// ---------------------------------------------------------------------------
// LayerNorm -> bf16 hi/lo split
// ---------------------------------------------------------------------------
__global__ void ln_kernel(const float* __restrict__ x, const float* __restrict__ gam,
                          const float* __restrict__ bet,
                          bf16* __restrict__ ohi, bf16* __restrict__ olo) {
    int row = blockIdx.x;
    const float* xr = x + (size_t)row * D_MODEL;
    float v[4];
    float s = 0.f, s2 = 0.f;
#pragma unroll
    for (int i = 0; i < 4; i++) {
        v[i] = xr[threadIdx.x + i * 256];
        s += v[i]; s2 += v[i] * v[i];
    }
#pragma unroll
    for (int o = 16; o > 0; o >>= 1) {
        s  += __shfl_xor_sync(~0u, s, o);
        s2 += __shfl_xor_sync(~0u, s2, o);
    }
    __shared__ float rs[8], rs2[8];
    int wid = threadIdx.x >> 5, lid = threadIdx.x & 31;
    if (lid == 0) { rs[wid] = s; rs2[wid] = s2; }
    __syncthreads();
    s = 0.f; s2 = 0.f;
#pragma unroll
    for (int i = 0; i < 8; i++) { s += rs[i]; s2 += rs2[i]; }
    float mu  = s * (1.f / D_MODEL);
    float var = s2 * (1.f / D_MODEL) - mu * mu;
    float inv = rsqrtf(var + 1e-5f);
#pragma unroll
    for (int i = 0; i < 4; i++) {
        int c = threadIdx.x + i * 256;
        float y = (v[i] - mu) * inv * gam[c] + bet[c];
        bf16 h = __float2bfloat16(y);
        ohi[(size_t)row * D_MODEL + c] = h;
        olo[(size_t)row * D_MODEL + c] = __float2bfloat16(y - __bfloat162float(h));
    }
}

// ---------------------------------------------------------------------------
// Transpose + bf16 split: W[K][N] -> out[N][K]
// ---------------------------------------------------------------------------
__global__ void tsplit_kernel(const float* __restrict__ W,
                              bf16* __restrict__ hi, bf16* __restrict__ lo,
                              int K, int N) {
    __shared__ float t[32][33];
    int n0 = blockIdx.x * 32, k0 = blockIdx.y * 32;
    int tx = threadIdx.x, ty = threadIdx.y;
#pragma unroll
    for (int j = 0; j < 4; j++)
        t[ty + j * 8][tx] = W[(size_t)(k0 + ty + j * 8) * N + n0 + tx];
    __syncthreads();
#pragma unroll
    for (int j = 0; j < 4; j++) {
        float v = t[tx][ty + j * 8];
        size_t o = (size_t)(n0 + ty + j * 8) * K + k0 + tx;
        bf16 h = __float2bfloat16(v);
        hi[o] = h;
        lo[o] = __float2bfloat16(v - __bfloat162float(h));
    }
}

// ---------------------------------------------------------------------------
// Pipelined HMMA GEMMs: 512 thr, block 128x128x64, warp tile 32x32
// ---------------------------------------------------------------------------
#define SA 72
#define GT_TILE2  (128 * SA * 2)          // 18432
#define GT_STG2   (4 * GT_TILE2)          // 73728
#define GEMM_SMEM (2 * GT_STG2)           // 147456

__device__ __forceinline__ void gemm_issue(
    uint32_t sb, int st, int kc, int bm, int bn, int tid, int K,
    const bf16* __restrict__ Ah, const bf16* __restrict__ Al,
    const bf16* __restrict__ Bh, const bf16* __restrict__ Bl) {
    int c0 = kc * 64;
    uint32_t base = sb + (uint32_t)st * GT_STG2;
#pragma unroll
    for (int it = 0; it < 2; it++) {
        int idx = tid + it * 512;
        int r = idx >> 3, cc = (idx & 7) * 8;
        size_t ga = (size_t)(bm * 128 + r) * K + c0 + cc;
        size_t gb = (size_t)(bn * 128 + r) * K + c0 + cc;
        uint32_t so = (uint32_t)(r * SA + cc) * 2;
        cp16(base + so, Ah + ga);
        cp16(base + GT_TILE2 + so, Al + ga);
        cp16(base + 2 * GT_TILE2 + so, Bh + gb);
        cp16(base + 3 * GT_TILE2 + so, Bl + gb);
    }
    CP_COMMIT();
}

#define GEMM_MAINLOOP(K_)                                                        \
    int a_row = wm * 32 + ((lane >> 3) & 1) * 8 + (lane & 7);                    \
    int a_kc  = (lane >> 4) * 8;                                                 \
    int b_row = wn * 32 + (lane >> 4) * 8 + (lane & 7);                          \
    int b_kc  = ((lane >> 3) & 1) * 8;                                           \
    float c[2][4][4];                                                            \
    _Pragma("unroll") for (int i = 0; i < 2; i++)                                \
    _Pragma("unroll") for (int j = 0; j < 4; j++)                                \
    _Pragma("unroll") for (int q = 0; q < 4; q++) c[i][j][q] = 0.f;              \
    const int NK = (K_) / 64;                                                    \
    gemm_issue(sb, 0, 0, bm, bn, tid, (K_), Ah, Al, Bh, Bl);                     \
    for (int kc = 0; kc < NK; kc++) {                                            \
        if (kc + 1 < NK) { gemm_issue(sb, (kc + 1) & 1, kc + 1, bm, bn, tid,     \
                                      (K_), Ah, Al, Bh, Bl); CP_WAIT1(); }       \
        else CP_WAIT0();                                                         \
        __syncthreads();                                                         \
        uint32_t uAh = sb + (kc & 1) * GT_STG2;                                  \
        uint32_t uAl = uAh + GT_TILE2;                                           \
        uint32_t uBh = uAh + 2 * GT_TILE2;                                       \
        uint32_t uBl = uAh + 3 * GT_TILE2;                                       \
        _Pragma("unroll")                                                        \
        for (int ks = 0; ks < 4; ks++) {                                         \
            uint32_t ah[2][4], al[2][4], bh[2][4], bl[2][4];                     \
            _Pragma("unroll")                                                    \
            for (int ma = 0; ma < 2; ma++) {                                     \
                uint32_t off = ((a_row + ma * 16) * SA + a_kc + ks * 16) * 2;    \
                LDSM4(ah[ma][0], ah[ma][1], ah[ma][2], ah[ma][3], uAh + off);    \
                LDSM4(al[ma][0], al[ma][1], al[ma][2], al[ma][3], uAl + off);    \
            }                                                                    \
            _Pragma("unroll")                                                    \
            for (int nb2 = 0; nb2 < 2; nb2++) {                                  \
                uint32_t off = ((b_row + nb2 * 16) * SA + b_kc + ks * 16) * 2;   \
                LDSM4(bh[nb2][0], bh[nb2][1], bh[nb2][2], bh[nb2][3], uBh + off);\
                LDSM4(bl[nb2][0], bl[nb2][1], bl[nb2][2], bl[nb2][3], uBl + off);\
            }                                                                    \
            _Pragma("unroll")                                                    \
            for (int ma = 0; ma < 2; ma++)                                       \
            _Pragma("unroll")                                                    \
            for (int nb = 0; nb < 4; nb++) {                                     \
                int n2 = nb >> 1, o = (nb & 1) * 2;                              \
                MMA16816(c[ma][nb], ah[ma], bh[n2][o], bh[n2][o + 1]);           \
                MMA16816(c[ma][nb], ah[ma], bl[n2][o], bl[n2][o + 1]);           \
                MMA16816(c[ma][nb], al[ma], bh[n2][o], bh[n2][o + 1]);           \
            }                                                                    \
        }                                                                        \
        __syncthreads();                                                         \
    }

__global__ void __launch_bounds__(512) gemm_mma_qkv(
    const bf16* __restrict__ Ah, const bf16* __restrict__ Al,
    const bf16* __restrict__ Bh, const bf16* __restrict__ Bl,
    const float* __restrict__ bias,
    bf16* __restrict__ qhi, bf16* __restrict__ qlo,
    bf16* __restrict__ khi, bf16* __restrict__ klo,
    bf16* __restrict__ vhi, bf16* __restrict__ vlo) {
    extern __shared__ char dyn[];
    uint32_t sb = smem_u32(dyn);
    int tid = threadIdx.x;
    int wid = tid >> 5, lane = tid & 31;
    int wm = wid & 3, wn = wid >> 2;
    int bm = blockIdx.y, bn = blockIdx.x;

    GEMM_MAINLOOP(D_MODEL)

    int r0 = bm * 128 + wm * 32 + (lane >> 2);
#pragma unroll
    for (int ma = 0; ma < 2; ma++) {
#pragma unroll
        for (int nb = 0; nb < 4; nb++) {
            int col = bn * 128 + wn * 32 + nb * 8 + (lane & 3) * 2;
            int hg = col >> 6;
            int sec = hg >> 4;
            int h = hg & 15;
            int c64 = col & 63;
            bf16* dh = (sec == 0) ? qhi : (sec == 1) ? khi : vhi;
            bf16* dl = (sec == 0) ? qlo : (sec == 1) ? klo : vlo;
            float bx = bias[col], by = bias[col + 1];
#pragma unroll
            for (int half = 0; half < 2; half++) {
                int row = r0 + ma * 16 + half * 8;
                int t = row & (T - 1), b = row >> 11;
                size_t idx = (((size_t)(b * NH + h)) * T + t) * DH + c64;
                float y0 = c[ma][nb][half * 2 + 0] + bx;
                float y1 = c[ma][nb][half * 2 + 1] + by;
                bf16 h0 = __float2bfloat16(y0);
                bf16 h1 = __float2bfloat16(y1);
                bf162 hv; hv.x = h0; hv.y = h1;
                bf162 lv;
                lv.x = __float2bfloat16(y0 - __bfloat162float(h0));
                lv.y = __float2bfloat16(y1 - __bfloat162float(h1));
                *(bf162*)&dh[idx] = hv;
                *(bf162*)&dl[idx] = lv;
            }
        }
    }
}

__global__ void __launch_bounds__(512) gemm_mma_out(
    const bf16* __restrict__ Ah, const bf16* __restrict__ Al,
    const bf16* __restrict__ Bh, const bf16* __restrict__ Bl,
    const float* __restrict__ bias, const float* __restrict__ res,
    float* __restrict__ C) {
    const int N = D_MODEL;
    extern __shared__ char dyn[];
    uint32_t sb = smem_u32(dyn);
    int tid = threadIdx.x;
    int wid = tid >> 5, lane = tid & 31;
    int wm = wid & 3, wn = wid >> 2;
    int bm = blockIdx.y, bn = blockIdx.x;

    GEMM_MAINLOOP(D_MODEL)

    int r0 = bm * 128 + wm * 32 + (lane >> 2);
#pragma unroll
    for (int ma = 0; ma < 2; ma++) {
#pragma unroll
        for (int nb = 0; nb < 4; nb++) {
            int col = bn * 128 + wn * 32 + nb * 8 + (lane & 3) * 2;
            int ra = r0 + ma * 16, rb = ra + 8;
            float2 o0, o1;
            o0.x = c[ma][nb][0] + bias[col];
            o0.y = c[ma][nb][1] + bias[col + 1];
            o1.x = c[ma][nb][2] + bias[col];
            o1.y = c[ma][nb][3] + bias[col + 1];
            float2 r2a = *(const float2*)&res[(size_t)ra * N + col];
            float2 r2b = *(const float2*)&res[(size_t)rb * N + col];
            o0.x += r2a.x; o0.y += r2a.y;
            o1.x += r2b.x; o1.y += r2b.y;
            *(float2*)&C[(size_t)ra * N + col] = o0;
            *(float2*)&C[(size_t)rb * N + col] = o1;
        }
    }
}

// ---------------------------------------------------------------------------
// Stats-only scores pass: per (row, 128-ktile) partial (m, sumexp). No S write.
// ---------------------------------------------------------------------------
#define SK 72
#define SCORES_SMEM (4 * 128 * SK * 2)

__global__ void __launch_bounds__(256) scores_stats(
    const bf16* __restrict__ qh, const bf16* __restrict__ ql,
    const bf16* __restrict__ kh, const bf16* __restrict__ kl,
    float2* __restrict__ part) {
    int kt = blockIdx.x, qt = blockIdx.y, bh = blockIdx.z;
    if (kt > qt) return;
    int tid = threadIdx.x;

    extern __shared__ char dyn[];
    bf16* sQh = (bf16*)dyn;
    bf16* sQl = sQh + 128 * SK;
    bf16* sKh = sQl + 128 * SK;
    bf16* sKl = sKh + 128 * SK;
    __shared__ float2 sstat[128][2];

    const bf16* qhb = qh + ((size_t)bh * T + qt * 128) * DH;
    const bf16* qlb = ql + ((size_t)bh * T + qt * 128) * DH;
    const bf16* khb = kh + ((size_t)bh * T + kt * 128) * DH;
    const bf16* klb = kl + ((size_t)bh * T + kt * 128) * DH;

#pragma unroll
    for (int it = 0; it < 4; it++) {
        int idx = tid + it * 256;
        int r = idx >> 3, cc = (idx & 7) * 8;
        int so = r * SK + cc;
        size_t go = (size_t)r * DH + cc;
        *(uint4*)&sQh[so] = *(const uint4*)&qhb[go];
        *(uint4*)&sQl[so] = *(const uint4*)&qlb[go];
        *(uint4*)&sKh[so] = *(const uint4*)&khb[go];
        *(uint4*)&sKl[so] = *(const uint4*)&klb[go];
    }
    __syncthreads();

    int wid = tid >> 5, lane = tid & 31;
    int wm = wid & 3, wn = wid >> 2;
    uint32_t uQh = smem_u32(sQh), uQl = smem_u32(sQl);
    uint32_t uKh = smem_u32(sKh), uKl = smem_u32(sKl);

    int a_row = wm * 32 + ((lane >> 3) & 1) * 8 + (lane & 7);
    int a_kc  = (lane >> 4) * 8;
    int b_row = wn * 64 + (lane >> 4) * 8 + (lane & 7);
    int b_kc  = ((lane >> 3) & 1) * 8;

    float c[2][8][4];
#pragma unroll
    for (int i = 0; i < 2; i++)
#pragma unroll
        for (int j = 0; j < 8; j++)
#pragma unroll
            for (int q = 0; q < 4; q++) c[i][j][q] = 0.f;

#pragma unroll
    for (int ks = 0; ks < 4; ks++) {
        uint32_t ah[2][4], al[2][4], bh2[4][4], bl2[4][4];
#pragma unroll
        for (int ma = 0; ma < 2; ma++) {
            uint32_t off = ((a_row + ma * 16) * SK + a_kc + ks * 16) * 2;
            LDSM4(ah[ma][0], ah[ma][1], ah[ma][2], ah[ma][3], uQh + off);
            LDSM4(al[ma][0], al[ma][1], al[ma][2], al[ma][3], uQl + off);
        }
#pragma unroll
        for (int nb2 = 0; nb2 < 4; nb2++) {
            uint32_t off = ((b_row + nb2 * 16) * SK + b_kc + ks * 16) * 2;
            LDSM4(bh2[nb2][0], bh2[nb2][1], bh2[nb2][2], bh2[nb2][3], uKh + off);
            LDSM4(bl2[nb2][0], bl2[nb2][1], bl2[nb2][2], bl2[nb2][3], uKl + off);
        }
#pragma unroll
        for (int ma = 0; ma < 2; ma++)
#pragma unroll
            for (int nb = 0; nb < 8; nb++) {
                int n2 = nb >> 1, o = (nb & 1) * 2;
                MMA16816(c[ma][nb], ah[ma], bh2[n2][o], bh2[n2][o + 1]);
                MMA16816(c[ma][nb], ah[ma], bl2[n2][o], bl2[n2][o + 1]);
                MMA16816(c[ma][nb], al[ma], bh2[n2][o], bh2[n2][o + 1]);
            }
    }

    bool diag = (qt == kt);
#pragma unroll
    for (int ma = 0; ma < 2; ma++) {
#pragma unroll
        for (int half = 0; half < 2; half++) {
            int lrow = wm * 32 + ma * 16 + half * 8 + (lane >> 2);
            float vv[8][2];
#pragma unroll
            for (int nb = 0; nb < 8; nb++) {
                int colc = wn * 64 + nb * 8 + (lane & 3) * 2;
                float v0 = c[ma][nb][half * 2 + 0] * 0.125f;
                float v1 = c[ma][nb][half * 2 + 1] * 0.125f;
                if (diag) {
                    if (colc > lrow) v0 = -1e30f;
                    if (colc + 1 > lrow) v1 = -1e30f;
                }
                vv[nb][0] = v0; vv[nb][1] = v1;
            }
            float mt = -1e30f;
#pragma unroll
            for (int nb = 0; nb < 8; nb++) {
                mt = fmaxf(mt, vv[nb][0]);
                mt = fmaxf(mt, vv[nb][1]);
            }
            float st = 0.f;
#pragma unroll
            for (int nb = 0; nb < 8; nb++) {
                st += __expf(vv[nb][0] - mt);
                st += __expf(vv[nb][1] - mt);
            }
#pragma unroll
            for (int o = 1; o < 4; o <<= 1) {
                float om = __shfl_xor_sync(~0u, mt, o);
                float os = __shfl_xor_sync(~0u, st, o);
                ms_merge(mt, st, om, os);
            }
            if ((lane & 3) == 0) sstat[lrow][wn] = make_float2(mt, st);
        }
    }
    __syncthreads();
    if (tid < 128) {
        float2 p0 = sstat[tid][0], p1 = sstat[tid][1];
        float m = p0.x, s = p0.y;
        ms_merge(m, s, p1.x, p1.y);
        part[((size_t)bh * T + qt * 128 + tid) * 16 + kt] = make_float2(m, s);
    }
}

// ---------------------------------------------------------------------------
// Reduce per-row partials -> (m, 1/sum)
// ---------------------------------------------------------------------------
__global__ void reduce_stats(const float2* __restrict__ part,
                             float* __restrict__ mA, float* __restrict__ invA) {
    int row = blockIdx.x * 256 + threadIdx.x;
    int r = row & (T - 1);
    int nkb = (r >> 7) + 1;
    float m = -1e30f, s = 0.f;
    const float2* p = part + (size_t)row * 16;
    for (int i = 0; i < nkb; i++) {
        float2 v = p[i];
        ms_merge(m, s, v.x, v.y);
    }
    mA[row] = m;
    invA[row] = 1.f / s;
}

// ---------------------------------------------------------------------------
// Fused av: recompute S (Q persistent in regs, K/V 64-chunks via cp.async),
// normalize in registers, write P fp32 to attn, repack c-frags -> a-frags
// (bf16 hi/lo), MMA with V -> O. Zero-fill upper triangle.
// 256 threads, 8 warps, each warp owns 16 q-rows.
// ---------------------------------------------------------------------------
#define FK 72
#define FA_QT2  (128 * FK * 2)            // 18432
#define FA_KT2  (64 * FK * 2)             // 9216
#define FA_STG  (4 * FA_KT2)              // 36864 (Kh,Kl,Vh,Vl)
#define FA_KV   (2 * FA_QT2)              // 36864
#define FA_SMEM (FA_KV + 2 * FA_STG)      // 110592

__device__ __forceinline__ void fa_issue_kv(
    uint32_t sb, int st, int kt, int tid,
    const bf16* __restrict__ kh, const bf16* __restrict__ kl,
    const bf16* __restrict__ vh, const bf16* __restrict__ vl) {
    uint32_t base = sb + FA_KV + (uint32_t)st * FA_STG;
#pragma unroll
    for (int p = 0; p < 2; p++) {
        int idx = tid + p * 256;
        int r = idx >> 3, cc = (idx & 7) * 8;
        size_t g = (size_t)(kt * 64 + r) * DH + cc;
        uint32_t so = (uint32_t)(r * FK + cc) * 2;
        cp16(base + so, kh + g);
        cp16(base + FA_KT2 + so, kl + g);
        cp16(base + 2 * FA_KT2 + so, vh + g);
        cp16(base + 3 * FA_KT2 + so, vl + g);
    }
    CP_COMMIT();
}

__global__ void __launch_bounds__(256) av_fused(
    const bf16* __restrict__ qhA, const bf16* __restrict__ qlA,
    const bf16* __restrict__ khA, const bf16* __restrict__ klA,
    const bf16* __restrict__ vhA, const bf16* __restrict__ vlA,
    const float* __restrict__ mA, const float* __restrict__ invA,
    float* __restrict__ attn,
    bf16* __restrict__ ohi, bf16* __restrict__ olo) {
    int qt = blockIdx.x, bh = blockIdx.y;
    int b = bh >> 4, h = bh & 15;
    int tid = threadIdx.x;
    int wid = tid >> 5, lane = tid & 31;

    extern __shared__ char dyn[];
    uint32_t sb = smem_u32(dyn);

    const bf16* qh = qhA + ((size_t)bh * T + qt * 128) * DH;
    const bf16* ql = qlA + ((size_t)bh * T + qt * 128) * DH;
    const bf16* kh = khA + (size_t)bh * T * DH;
    const bf16* kl = klA + (size_t)bh * T * DH;
    const bf16* vh = vhA + (size_t)bh * T * DH;
    const bf16* vl = vlA + (size_t)bh * T * DH;
    float* sblk = attn + ((size_t)bh * T + qt * 128) * T;

    // Per-thread softmax stats (rows fixed per thread)
    int lr0 = wid * 16 + (lane >> 2);          // local row for c0,c1
    int lr1 = lr0 + 8;                          // local row for c2,c3
    int qrow0 = qt * 128 + lr0, qrow1 = qt * 128 + lr1;
    float m0 = mA[bh * T + qrow0], iv0 = invA[bh * T + qrow0];
    float m1 = mA[bh * T + qrow1], iv1 = invA[bh * T + qrow1];

    // Issue Q tiles (group 0) and stage 0 (group 1)
    {
#pragma unroll
        for (int p = 0; p < 4; p++) {
            int idx = tid + p * 256;
            int r = idx >> 3, cc = (idx & 7) * 8;
            size_t g = (size_t)r * DH + cc;
            uint32_t so = (uint32_t)(r * FK + cc) * 2;
            cp16(sb + so, qh + g);
            cp16(sb + FA_QT2 + so, ql + g);
        }
        CP_COMMIT();
    }
    fa_issue_kv(sb, 0, 0, tid, kh, kl, vh, vl);

    // Fragment addressing
    int a_row = wid * 16 + ((lane >> 3) & 1) * 8 + (lane & 7);
    int a_kc  = (lane >> 4) * 8;
    int b_row8 = (lane >> 4) * 8 + (lane & 7);
    int b_kc  = ((lane >> 3) & 1) * 8;
    int v_k   = lane & 15;
    int v_n   = (lane >> 4) * 8;

    uint32_t qa_h[4][4], qa_l[4][4];
    float o[8][4];
#pragma unroll
    for (int i = 0; i < 8; i++)
#pragma unroll
        for (int q = 0; q < 4; q++) o[i][q] = 0.f;

    int nk = 2 * qt + 2;
    for (int kt = 0; kt < nk; kt++) {
        if (kt + 1 < nk) { fa_issue_kv(sb, (kt + 1) & 1, kt + 1, tid, kh, kl, vh, vl); CP_WAIT1(); }
        else CP_WAIT0();
        __syncthreads();

        if (kt == 0) {
            // Q fragments (persistent)
#pragma unroll
            for (int ks = 0; ks < 4; ks++) {
                uint32_t off = (a_row * FK + a_kc + ks * 16) * 2;
                LDSM4(qa_h[ks][0], qa_h[ks][1], qa_h[ks][2], qa_h[ks][3], sb + off);
                LDSM4(qa_l[ks][0], qa_l[ks][1], qa_l[ks][2], qa_l[ks][3], sb + FA_QT2 + off);
            }
        }

        uint32_t uKh = sb + FA_KV + (uint32_t)(kt & 1) * FA_STG;
        uint32_t uKl = uKh + FA_KT2;
        uint32_t uVh = uKh + 2 * FA_KT2;
        uint32_t uVl = uKh + 3 * FA_KT2;

        // --- S = Q K^T (3-term split), 16 q-rows x 64 keys per warp ---
        float s[8][4];
#pragma unroll
        for (int i = 0; i < 8; i++)
#pragma unroll
            for (int q = 0; q < 4; q++) s[i][q] = 0.f;

#pragma unroll
        for (int ks = 0; ks < 4; ks++) {
            uint32_t kbh[4][4], kbl[4][4];
#pragma unroll
            for (int nb2 = 0; nb2 < 4; nb2++) {
                uint32_t off = ((nb2 * 16 + b_row8) * FK + b_kc + ks * 16) * 2;
                LDSM4(kbh[nb2][0], kbh[nb2][1], kbh[nb2][2], kbh[nb2][3], uKh + off);
                LDSM4(kbl[nb2][0], kbl[nb2][1], kbl[nb2][2], kbl[nb2][3], uKl + off);
            }
#pragma unroll
            for (int nb = 0; nb < 8; nb++) {
                int n2 = nb >> 1, oo = (nb & 1) * 2;
                MMA16816(s[nb], qa_h[ks], kbh[n2][oo], kbh[n2][oo + 1]);
                MMA16816(s[nb], qa_h[ks], kbl[n2][oo], kbl[n2][oo + 1]);
                MMA16816(s[nb], qa_l[ks], kbh[n2][oo], kbh[n2][oo + 1]);
            }
        }

        // --- normalize, write P, repack to a-frags (bf16 hi/lo) ---
        uint32_t pa_h[4][4], pa_l[4][4];
#pragma unroll
        for (int nb = 0; nb < 8; nb++) {
            int kcol = kt * 64 + nb * 8 + (lane & 3) * 2;
            float p0 = (kcol     <= qrow0) ? __expf(s[nb][0] * 0.125f - m0) * iv0 : 0.f;
            float p1 = (kcol + 1 <= qrow0) ? __expf(s[nb][1] * 0.125f - m0) * iv0 : 0.f;
            float p2 = (kcol     <= qrow1) ? __expf(s[nb][2] * 0.125f - m1) * iv1 : 0.f;
            float p3 = (kcol + 1 <= qrow1) ? __expf(s[nb][3] * 0.125f - m1) * iv1 : 0.f;
            float2 w0; w0.x = p0; w0.y = p1;
            float2 w1; w1.x = p2; w1.y = p3;
            *(float2*)&sblk[(size_t)lr0 * T + kcol] = w0;
            *(float2*)&sblk[(size_t)lr1 * T + kcol] = w1;
            // split
            bf16 h0 = __float2bfloat16(p0), h1b = __float2bfloat16(p1);
            bf16 h2 = __float2bfloat16(p2), h3 = __float2bfloat16(p3);
            float l0f = p0 - __bfloat162float(h0), l1f = p1 - __bfloat162float(h1b);
            float l2f = p2 - __bfloat162float(h2), l3f = p3 - __bfloat162float(h3);
            int j = nb >> 1, hf = (nb & 1) * 2;
            bf162 t0; t0.x = h0; t0.y = h1b;
            bf162 t1; t1.x = h2; t1.y = h3;
            pa_h[j][hf]     = *(uint32_t*)&t0;
            pa_h[j][hf + 1] = *(uint32_t*)&t1;
            pa_l[j][hf]     = packbf(l0f, l1f);
            pa_l[j][hf + 1] = packbf(l2f, l3f);
        }

        // --- O += P V (3-term split) ---
#pragma unroll
        for (int j = 0; j < 4; j++) {
            uint32_t vbh[4][4], vbl[4][4];
#pragma unroll
            for (int ns = 0; ns < 4; ns++) {
                uint32_t off = ((j * 16 + v_k) * FK + ns * 16 + v_n) * 2;
                LDSM4T(vbh[ns][0], vbh[ns][1], vbh[ns][2], vbh[ns][3], uVh + off);
                LDSM4T(vbl[ns][0], vbl[ns][1], vbl[ns][2], vbl[ns][3], uVl + off);
            }
#pragma unroll
            for (int nb = 0; nb < 8; nb++) {
                int n2 = nb >> 1, oo = (nb & 1) * 2;
                MMA16816(o[nb], pa_h[j], vbh[n2][oo], vbh[n2][oo + 1]);
                MMA16816(o[nb], pa_h[j], vbl[n2][oo], vbl[n2][oo + 1]);
                MMA16816(o[nb], pa_l[j], vbh[n2][oo], vbh[n2][oo + 1]);
            }
        }
        __syncthreads();
    }

    // Zero-fill upper triangle cols [(qt+1)*128, T)
    {
        int c0u = (qt + 1) * 128;
        int r = tid >> 1, hf = tid & 1;
        float4 z = make_float4(0.f, 0.f, 0.f, 0.f);
        for (int cc = c0u + hf * 4; cc < T; cc += 8)
            *(float4*)&sblk[(size_t)r * T + cc] = z;
    }

    // O epilogue -> bf16 hi/lo
#pragma unroll
    for (int nb = 0; nb < 8; nb++) {
        int d = nb * 8 + (lane & 3) * 2;
        size_t i0 = ((size_t)(b * T + qrow0)) * D_MODEL + h * DH + d;
        size_t i1 = ((size_t)(b * T + qrow1)) * D_MODEL + h * DH + d;
        float y0 = o[nb][0], y1 = o[nb][1], y2 = o[nb][2], y3 = o[nb][3];
        bf16 h0 = __float2bfloat16(y0), h1b = __float2bfloat16(y1);
        bf16 h2 = __float2bfloat16(y2), h3 = __float2bfloat16(y3);
        bf162 hv0; hv0.x = h0; hv0.y = h1b;
        bf162 hv1; hv1.x = h2; hv1.y = h3;
        *(bf162*)&ohi[i0] = hv0;
        *(bf162*)&ohi[i1] = hv1;
        bf162 lv0, lv1;
        lv0.x = __float2bfloat16(y0 - __bfloat162float(h0));
        lv0.y = __float2bfloat16(y1 - __bfloat162float(h1b));
        lv1.x = __float2bfloat16(y2 - __bfloat162float(h2));
        lv1.y = __float2bfloat16(y3 - __bfloat162float(h3));
        *(bf162*)&olo[i0] = lv0;
        *(bf162*)&olo[i1] = lv1;
    }
}

// ---------------------------------------------------------------------------
extern "C" void kernel_launch(void* const* d_in, const int* in_sizes, int n_in,
                              void* d_out, int out_size) {
    (void)in_sizes; (void)n_in; (void)out_size;
    const float* x     = (const float*)d_in[0];
    const float* ln_g  = (const float*)d_in[1];
    const float* ln_b  = (const float*)d_in[2];
    const float* qkv_w = (const float*)d_in[3];
    const float* qkv_b = (const float*)d_in[4];
    const float* out_w = (const float*)d_in[5];
    const float* out_b = (const float*)d_in[6];

    float* xout = (float*)d_out;
    float* attn = xout + (size_t)BT * D_MODEL;

    static bf16 *p_hhi = nullptr, *p_hlo, *p_wqh, *p_wql, *p_woh, *p_wol;
    static bf16 *p_qh, *p_ql, *p_kh, *p_kl, *p_vh, *p_vl, *p_aoh, *p_aol;
    static float2* p_part;
    static float *p_m, *p_inv;
    if (!p_hhi) {
        cudaGetSymbolAddress((void**)&p_hhi, g_h_hi);
        cudaGetSymbolAddress((void**)&p_hlo, g_h_lo);
        cudaGetSymbolAddress((void**)&p_wqh, g_wq_hi);
        cudaGetSymbolAddress((void**)&p_wql, g_wq_lo);
        cudaGetSymbolAddress((void**)&p_woh, g_wo_hi);
        cudaGetSymbolAddress((void**)&p_wol, g_wo_lo);
        cudaGetSymbolAddress((void**)&p_qh, g_q_hi);
        cudaGetSymbolAddress((void**)&p_ql, g_q_lo);
        cudaGetSymbolAddress((void**)&p_kh, g_k_hi);
        cudaGetSymbolAddress((void**)&p_kl, g_k_lo);
        cudaGetSymbolAddress((void**)&p_vh, g_v_hi);
        cudaGetSymbolAddress((void**)&p_vl, g_v_lo);
        cudaGetSymbolAddress((void**)&p_aoh, g_ao_hi);
        cudaGetSymbolAddress((void**)&p_aol, g_ao_lo);
        cudaGetSymbolAddress((void**)&p_part, g_part);
        cudaGetSymbolAddress((void**)&p_m, g_m);
        cudaGetSymbolAddress((void**)&p_inv, g_inv);
        cudaFuncSetAttribute(gemm_mma_qkv, cudaFuncAttributeMaxDynamicSharedMemorySize, GEMM_SMEM);
        cudaFuncSetAttribute(gemm_mma_out, cudaFuncAttributeMaxDynamicSharedMemorySize, GEMM_SMEM);
        cudaFuncSetAttribute(scores_stats, cudaFuncAttributeMaxDynamicSharedMemorySize, SCORES_SMEM);
        cudaFuncSetAttribute(av_fused, cudaFuncAttributeMaxDynamicSharedMemorySize, FA_SMEM);
    }

    ln_kernel<<<BT, 256>>>(x, ln_g, ln_b, p_hhi, p_hlo);
    tsplit_kernel<<<dim3(QKV_N / 32, D_MODEL / 32), dim3(32, 8)>>>(qkv_w, p_wqh, p_wql, D_MODEL, QKV_N);
    tsplit_kernel<<<dim3(D_MODEL / 32, D_MODEL / 32), dim3(32, 8)>>>(out_w, p_woh, p_wol, D_MODEL, D_MODEL);

    gemm_mma_qkv<<<dim3(QKV_N / 128, BT / 128), 512, GEMM_SMEM>>>(
        p_hhi, p_hlo, p_wqh, p_wql, qkv_b, p_qh, p_ql, p_kh, p_kl, p_vh, p_vl);

    scores_stats<<<dim3(16, 16, 32), 256, SCORES_SMEM>>>(p_qh, p_ql, p_kh, p_kl, p_part);
    reduce_stats<<<(32 * T) / 256, 256>>>(p_part, p_m, p_inv);
    av_fused<<<dim3(16, 32), 256, FA_SMEM>>>(p_qh, p_ql, p_kh, p_kl, p_vh, p_vl,
                                             p_m, p_inv, attn, p_aoh, p_aol);

    gemm_mma_out<<<dim3(D_MODEL / 128, BT / 128), 512, GEMM_SMEM>>>(
        p_aoh, p_aol, p_woh, p_wol, out_b, x, xout);
}